// round 3
// baseline (speedup 1.0000x reference)
#include <cuda_runtime.h>

#define NMAX 100000
#define D 128

// Scratch (device globals; allocation inside kernel_launch is forbidden)
__device__ float g_y1[NMAX * D];     // spmm(x)
__device__ float g_y2[NMAX * D];     // spmm(spmm(x))
__device__ float g_deg[NMAX];
__device__ float g_dinv[NMAX];
__device__ float g_dinv2[NMAX];

// ---------------------------------------------------------------------------
// Zero scratch
// ---------------------------------------------------------------------------
__global__ void zero_kernel(int n) {
    int total = n * D;
    for (int i = blockIdx.x * blockDim.x + threadIdx.x; i < total;
         i += gridDim.x * blockDim.x) {
        g_y1[i] = 0.f;
        g_y2[i] = 0.f;
        if (i < n) g_deg[i] = 0.f;
    }
}

// ---------------------------------------------------------------------------
// SpMM: dst[row] += src[col] for each edge. Warp per edge, float4 per lane.
// Edge indices are int32 (JAX default x64-disabled downcasts int64 request).
// Bounds guard: if dtype assumption is wrong we produce wrong numbers, not IMA.
// ---------------------------------------------------------------------------
__global__ void spmm_kernel(const float* __restrict__ src,
                            float* __restrict__ dst,
                            const int* __restrict__ rows,
                            const int* __restrict__ cols,
                            int E, int n, int countDeg) {
    int lane = threadIdx.x & 31;
    int warp = (blockIdx.x * blockDim.x + threadIdx.x) >> 5;
    int nw = (gridDim.x * blockDim.x) >> 5;
    for (int e = warp; e < E; e += nw) {
        int r = rows[e];
        int c = cols[e];
        if ((unsigned)r >= (unsigned)n || (unsigned)c >= (unsigned)n) continue;
        float4 v = *reinterpret_cast<const float4*>(src + (size_t)c * D + lane * 4);
        float* d = dst + (size_t)r * D + lane * 4;
        atomicAdd(d + 0, v.x);
        atomicAdd(d + 1, v.y);
        atomicAdd(d + 2, v.z);
        atomicAdd(d + 3, v.w);
        if (countDeg && lane == 0) atomicAdd(&g_deg[r], 1.0f);
    }
}

// ---------------------------------------------------------------------------
// deg -> 1/max(deg,1) and its square
// ---------------------------------------------------------------------------
__global__ void dinv_kernel(int n) {
    int i = blockIdx.x * blockDim.x + threadIdx.x;
    if (i < n) {
        float d = fmaxf(g_deg[i], 1.0f);
        float v = 1.0f / d;
        g_dinv[i] = v;
        g_dinv2[i] = v * v;
    }
}

// ---------------------------------------------------------------------------
// Fused branch GEMM:
//   R = relu((A * scale) @ W + bias)        [64 x 128 tile per block]
//   out (+)= R @ Wc (+ bcls for ego branch) [64 x 16]
// Block: 256 threads. BM=64, BN=128, K=128 (single slab, no k-pipeline).
// Thread microtile: 8 rows x 4 cols.  smem: W(64KB) + A^T/Relu union + Wc.
// ---------------------------------------------------------------------------
__global__ void gemm_branch(const float* __restrict__ A,
                            const float* __restrict__ scale,   // null => 1.0
                            const float* __restrict__ W,       // [128,128]
                            const float* __restrict__ bias,    // [128]
                            const float* __restrict__ Wc,      // [128,16]
                            const float* __restrict__ bcls,    // [16] (ego only)
                            float* __restrict__ out,           // [n,16]
                            int n, int ego) {
    extern __shared__ float sm[];
    float* sB  = sm;                    // 128*128 = 16384 floats
    float* sS  = sm + 128 * 128;        // union: A^T [128][64] then Relu [64][132]
    float* sWc = sS + 64 * 132;         // 128*16 = 2048 floats

    int tid = threadIdx.x;
    int rowBase = blockIdx.x * 64;

    // Load W into smem (straight copy, [k][n])
    {
        const float4* Wv = reinterpret_cast<const float4*>(W);
        float4* sBv = reinterpret_cast<float4*>(sB);
        for (int q = tid; q < 128 * 32; q += 256) sBv[q] = Wv[q];
    }
    // Load Wc into smem
    {
        const float4* Wv = reinterpret_cast<const float4*>(Wc);
        float4* sv = reinterpret_cast<float4*>(sWc);
        for (int q = tid; q < 128 * 4; q += 256) sv[q] = Wv[q];
    }
    // Load A tile transposed (sS[k][m], stride 64) with optional row scale
    for (int q = tid; q < 64 * 32; q += 256) {
        int row = q >> 5;
        int c4 = q & 31;
        int gr = rowBase + row;
        float4 v = make_float4(0.f, 0.f, 0.f, 0.f);
        if (gr < n) {
            v = *reinterpret_cast<const float4*>(A + (size_t)gr * 128 + c4 * 4);
            if (scale) {
                float s = scale[gr];
                v.x *= s; v.y *= s; v.z *= s; v.w *= s;
            }
        }
        int k = c4 * 4;
        sS[(k + 0) * 64 + row] = v.x;
        sS[(k + 1) * 64 + row] = v.y;
        sS[(k + 2) * 64 + row] = v.z;
        sS[(k + 3) * 64 + row] = v.w;
    }
    __syncthreads();

    int mt = tid >> 5;   // 0..7  (row group: rows mt*8 .. mt*8+7)
    int nt = tid & 31;   // 0..31 (col group: cols nt*4 .. nt*4+3)
    float4 bb = *reinterpret_cast<const float4*>(bias + nt * 4);

    float acc[8][4];
#pragma unroll
    for (int i = 0; i < 8; i++)
#pragma unroll
        for (int j = 0; j < 4; j++) acc[i][j] = 0.f;

#pragma unroll 4
    for (int k = 0; k < 128; k++) {
        float4 b4 = *reinterpret_cast<const float4*>(sB + k * 128 + nt * 4);
        float4 a0 = *reinterpret_cast<const float4*>(sS + k * 64 + mt * 8);
        float4 a1 = *reinterpret_cast<const float4*>(sS + k * 64 + mt * 8 + 4);
        float a[8] = {a0.x, a0.y, a0.z, a0.w, a1.x, a1.y, a1.z, a1.w};
#pragma unroll
        for (int i = 0; i < 8; i++) {
            acc[i][0] += a[i] * b4.x;
            acc[i][1] += a[i] * b4.y;
            acc[i][2] += a[i] * b4.z;
            acc[i][3] += a[i] * b4.w;
        }
    }
    __syncthreads();  // everyone done reading A^T before overwriting as Relu

    // bias + relu, stash tile in smem ([64][132] padded: stride 132 kills
    // the 8-way conflict in the second GEMM's column reads)
#pragma unroll
    for (int i = 0; i < 8; i++) {
        float4 r;
        r.x = fmaxf(acc[i][0] + bb.x, 0.f);
        r.y = fmaxf(acc[i][1] + bb.y, 0.f);
        r.z = fmaxf(acc[i][2] + bb.z, 0.f);
        r.w = fmaxf(acc[i][3] + bb.w, 0.f);
        *reinterpret_cast<float4*>(sS + (mt * 8 + i) * 132 + nt * 4) = r;
    }
    __syncthreads();

    // Second GEMM: [64x128] @ [128x16]. Thread -> (m, jg): 4 output cols.
    int m = tid >> 2;
    int jg = tid & 3;
    float4 acc2 = make_float4(0.f, 0.f, 0.f, 0.f);
#pragma unroll 8
    for (int nn = 0; nn < 128; nn++) {
        float h = sS[m * 132 + nn];
        float4 w = *reinterpret_cast<const float4*>(sWc + nn * 16 + jg * 4);
        acc2.x += h * w.x;
        acc2.y += h * w.y;
        acc2.z += h * w.z;
        acc2.w += h * w.w;
    }
    int gr = rowBase + m;
    if (gr < n) {
        float4* o = reinterpret_cast<float4*>(out + (size_t)gr * 16 + jg * 4);
        if (ego) {
            float4 bc = *reinterpret_cast<const float4*>(bcls + jg * 4);
            acc2.x += bc.x; acc2.y += bc.y; acc2.z += bc.z; acc2.w += bc.w;
            *o = acc2;   // first branch initializes out
        } else {
            float4 cur = *o;
            cur.x += acc2.x; cur.y += acc2.y; cur.z += acc2.z; cur.w += acc2.w;
            *o = cur;
        }
    }
}

// ---------------------------------------------------------------------------
// Launcher
// ---------------------------------------------------------------------------
extern "C" void kernel_launch(void* const* d_in, const int* in_sizes, int n_in,
                              void* d_out, int out_size) {
    const float* x          = (const float*)d_in[0];
    const int*   ei         = (const int*)d_in[1];     // int32! (JAX x64 off)
    const float* W_ego      = (const float*)d_in[2];
    const float* b_ego      = (const float*)d_in[3];
    const float* W_h1       = (const float*)d_in[4];
    const float* b_h1       = (const float*)d_in[5];
    const float* W_h2       = (const float*)d_in[6];
    const float* b_h2       = (const float*)d_in[7];
    const float* W_cls      = (const float*)d_in[8];
    const float* b_cls      = (const float*)d_in[9];
    float* out = (float*)d_out;

    int n = in_sizes[0] / D;        // 100000
    int E = in_sizes[1] / 2;        // 1600000
    const int* rows = ei;
    const int* cols = ei + E;

    float *y1, *y2, *dinv, *dinv2;
    cudaGetSymbolAddress((void**)&y1, g_y1);
    cudaGetSymbolAddress((void**)&y2, g_y2);
    cudaGetSymbolAddress((void**)&dinv, g_dinv);
    cudaGetSymbolAddress((void**)&dinv2, g_dinv2);

    const int SMEM = (128 * 128 + 64 * 132 + 128 * 16) * 4;  // 107520 B
    cudaFuncSetAttribute(gemm_branch,
                         cudaFuncAttributeMaxDynamicSharedMemorySize, SMEM);

    zero_kernel<<<2048, 256>>>(n);
    spmm_kernel<<<4096, 256>>>(x, y1, rows, cols, E, n, 1);
    dinv_kernel<<<(n + 255) / 256, 256>>>(n);
    spmm_kernel<<<4096, 256>>>(y1, y2, rows, cols, E, n, 0);

    int gb = (n + 63) / 64;
    gemm_branch<<<gb, 256, SMEM>>>(x,  nullptr, W_ego, b_ego,
                                   W_cls,              b_cls,   out, n, 1);
    gemm_branch<<<gb, 256, SMEM>>>(y1, dinv,    W_h1,  b_h1,
                                   W_cls + 128 * 16,   nullptr, out, n, 0);
    gemm_branch<<<gb, 256, SMEM>>>(y2, dinv2,   W_h2,  b_h2,
                                   W_cls + 256 * 16,   nullptr, out, n, 0);
}

// round 4
// speedup vs baseline: 1.8049x; 1.8049x over previous
#include <cuda_runtime.h>

#define NMAX 100000
#define EMAX 1600000
#define D 128

// Scratch (device globals; allocation is forbidden)
__device__ float g_y1[NMAX * D];     // spmm(x)
__device__ float g_y2[NMAX * D];     // spmm(spmm(x))
__device__ float g_dinv[NMAX];
__device__ float g_dinv2[NMAX];
__device__ int   g_cnt[NMAX];        // per-row edge count (degree)
__device__ int   g_rowptr[NMAX + 1];
__device__ int   g_cursor[NMAX];
__device__ int   g_csrcol[EMAX];

// ---------------------------------------------------------------------------
__global__ void zero_cnt(int n) {
    int i = blockIdx.x * blockDim.x + threadIdx.x;
    if (i < n) g_cnt[i] = 0;
}

__global__ void count_kernel(const int* __restrict__ rows, int E, int n) {
    int e = blockIdx.x * blockDim.x + threadIdx.x;
    if (e < E) {
        int r = rows[e];
        if ((unsigned)r < (unsigned)n) atomicAdd(&g_cnt[r], 1);
    }
}

// Single-block exclusive scan of g_cnt -> g_rowptr / g_cursor
__global__ void scan_kernel(int n) {
    __shared__ int ssum[1024];
    int tid = threadIdx.x;
    int chunk = (n + 1023) >> 10;
    int start = tid * chunk;
    int end = min(start + chunk, n);
    int local = 0;
    for (int i = start; i < end; i++) local += g_cnt[i];
    ssum[tid] = local;
    __syncthreads();
    // Hillis-Steele inclusive scan
    for (int off = 1; off < 1024; off <<= 1) {
        int v = (tid >= off) ? ssum[tid - off] : 0;
        __syncthreads();
        ssum[tid] += v;
        __syncthreads();
    }
    int run = (tid == 0) ? 0 : ssum[tid - 1];
    for (int i = start; i < end; i++) {
        int c = g_cnt[i];
        g_rowptr[i] = run;
        g_cursor[i] = run;
        run += c;
    }
    if (tid == 1023) g_rowptr[n] = ssum[1023];
}

__global__ void scatter_kernel(const int* __restrict__ rows,
                               const int* __restrict__ cols, int E, int n) {
    int e = blockIdx.x * blockDim.x + threadIdx.x;
    if (e < E) {
        int r = rows[e];
        int c = cols[e];
        if ((unsigned)r < (unsigned)n && (unsigned)c < (unsigned)n) {
            int pos = atomicAdd(&g_cursor[r], 1);
            g_csrcol[pos] = c;
        }
    }
}

__global__ void dinv_kernel(int n) {
    int i = blockIdx.x * blockDim.x + threadIdx.x;
    if (i < n) {
        float d = fmaxf((float)g_cnt[i], 1.0f);
        float v = 1.0f / d;
        g_dinv[i] = v;
        g_dinv2[i] = v * v;
    }
}

// ---------------------------------------------------------------------------
// SpMM gather: warp per row. dst[r] = sum_{c in N(r)} src[c].
// Each lane owns 4 consecutive floats (float4). Unroll x4 for MLP.
// ---------------------------------------------------------------------------
__global__ void spmm_gather(const float* __restrict__ src,
                            float* __restrict__ dst, int n) {
    int lane = threadIdx.x & 31;
    int warp = (blockIdx.x * blockDim.x + threadIdx.x) >> 5;
    int nw = (gridDim.x * blockDim.x) >> 5;
    for (int r = warp; r < n; r += nw) {
        int s = g_rowptr[r];
        int e = g_rowptr[r + 1];
        float4 a0 = make_float4(0.f, 0.f, 0.f, 0.f);
        float4 a1 = make_float4(0.f, 0.f, 0.f, 0.f);
        float4 a2 = make_float4(0.f, 0.f, 0.f, 0.f);
        float4 a3 = make_float4(0.f, 0.f, 0.f, 0.f);
        int j = s;
        for (; j + 3 < e; j += 4) {
            int c0 = g_csrcol[j + 0];
            int c1 = g_csrcol[j + 1];
            int c2 = g_csrcol[j + 2];
            int c3 = g_csrcol[j + 3];
            float4 v0 = *reinterpret_cast<const float4*>(src + (size_t)c0 * D + lane * 4);
            float4 v1 = *reinterpret_cast<const float4*>(src + (size_t)c1 * D + lane * 4);
            float4 v2 = *reinterpret_cast<const float4*>(src + (size_t)c2 * D + lane * 4);
            float4 v3 = *reinterpret_cast<const float4*>(src + (size_t)c3 * D + lane * 4);
            a0.x += v0.x; a0.y += v0.y; a0.z += v0.z; a0.w += v0.w;
            a1.x += v1.x; a1.y += v1.y; a1.z += v1.z; a1.w += v1.w;
            a2.x += v2.x; a2.y += v2.y; a2.z += v2.z; a2.w += v2.w;
            a3.x += v3.x; a3.y += v3.y; a3.z += v3.z; a3.w += v3.w;
        }
        for (; j < e; j++) {
            int c = g_csrcol[j];
            float4 v = *reinterpret_cast<const float4*>(src + (size_t)c * D + lane * 4);
            a0.x += v.x; a0.y += v.y; a0.z += v.z; a0.w += v.w;
        }
        float4 acc;
        acc.x = (a0.x + a1.x) + (a2.x + a3.x);
        acc.y = (a0.y + a1.y) + (a2.y + a3.y);
        acc.z = (a0.z + a1.z) + (a2.z + a3.z);
        acc.w = (a0.w + a1.w) + (a2.w + a3.w);
        *reinterpret_cast<float4*>(dst + (size_t)r * D + lane * 4) = acc;
    }
}

// ---------------------------------------------------------------------------
// Fused branch GEMM (unchanged from R3):
//   R = relu((A * scale) @ W + bias);  out (+)= R @ Wc (+ bcls for ego)
// ---------------------------------------------------------------------------
__global__ void gemm_branch(const float* __restrict__ A,
                            const float* __restrict__ scale,   // null => 1.0
                            const float* __restrict__ W,       // [128,128]
                            const float* __restrict__ bias,    // [128]
                            const float* __restrict__ Wc,      // [128,16]
                            const float* __restrict__ bcls,    // [16] (ego only)
                            float* __restrict__ out,           // [n,16]
                            int n, int ego) {
    extern __shared__ float sm[];
    float* sB  = sm;                    // 128*128
    float* sS  = sm + 128 * 128;        // union: A^T [128][64] then Relu [64][132]
    float* sWc = sS + 64 * 132;         // 128*16

    int tid = threadIdx.x;
    int rowBase = blockIdx.x * 64;

    {
        const float4* Wv = reinterpret_cast<const float4*>(W);
        float4* sBv = reinterpret_cast<float4*>(sB);
        for (int q = tid; q < 128 * 32; q += 256) sBv[q] = Wv[q];
    }
    {
        const float4* Wv = reinterpret_cast<const float4*>(Wc);
        float4* sv = reinterpret_cast<float4*>(sWc);
        for (int q = tid; q < 128 * 4; q += 256) sv[q] = Wv[q];
    }
    for (int q = tid; q < 64 * 32; q += 256) {
        int row = q >> 5;
        int c4 = q & 31;
        int gr = rowBase + row;
        float4 v = make_float4(0.f, 0.f, 0.f, 0.f);
        if (gr < n) {
            v = *reinterpret_cast<const float4*>(A + (size_t)gr * 128 + c4 * 4);
            if (scale) {
                float s = scale[gr];
                v.x *= s; v.y *= s; v.z *= s; v.w *= s;
            }
        }
        int k = c4 * 4;
        sS[(k + 0) * 64 + row] = v.x;
        sS[(k + 1) * 64 + row] = v.y;
        sS[(k + 2) * 64 + row] = v.z;
        sS[(k + 3) * 64 + row] = v.w;
    }
    __syncthreads();

    int mt = tid >> 5;
    int nt = tid & 31;
    float4 bb = *reinterpret_cast<const float4*>(bias + nt * 4);

    float acc[8][4];
#pragma unroll
    for (int i = 0; i < 8; i++)
#pragma unroll
        for (int j = 0; j < 4; j++) acc[i][j] = 0.f;

#pragma unroll 4
    for (int k = 0; k < 128; k++) {
        float4 b4 = *reinterpret_cast<const float4*>(sB + k * 128 + nt * 4);
        float4 a0 = *reinterpret_cast<const float4*>(sS + k * 64 + mt * 8);
        float4 a1 = *reinterpret_cast<const float4*>(sS + k * 64 + mt * 8 + 4);
        float a[8] = {a0.x, a0.y, a0.z, a0.w, a1.x, a1.y, a1.z, a1.w};
#pragma unroll
        for (int i = 0; i < 8; i++) {
            acc[i][0] += a[i] * b4.x;
            acc[i][1] += a[i] * b4.y;
            acc[i][2] += a[i] * b4.z;
            acc[i][3] += a[i] * b4.w;
        }
    }
    __syncthreads();

#pragma unroll
    for (int i = 0; i < 8; i++) {
        float4 r;
        r.x = fmaxf(acc[i][0] + bb.x, 0.f);
        r.y = fmaxf(acc[i][1] + bb.y, 0.f);
        r.z = fmaxf(acc[i][2] + bb.z, 0.f);
        r.w = fmaxf(acc[i][3] + bb.w, 0.f);
        *reinterpret_cast<float4*>(sS + (mt * 8 + i) * 132 + nt * 4) = r;
    }
    __syncthreads();

    int m = tid >> 2;
    int jg = tid & 3;
    float4 acc2 = make_float4(0.f, 0.f, 0.f, 0.f);
#pragma unroll 8
    for (int nn = 0; nn < 128; nn++) {
        float h = sS[m * 132 + nn];
        float4 w = *reinterpret_cast<const float4*>(sWc + nn * 16 + jg * 4);
        acc2.x += h * w.x;
        acc2.y += h * w.y;
        acc2.z += h * w.z;
        acc2.w += h * w.w;
    }
    int gr = rowBase + m;
    if (gr < n) {
        float4* o = reinterpret_cast<float4*>(out + (size_t)gr * 16 + jg * 4);
        if (ego) {
            float4 bc = *reinterpret_cast<const float4*>(bcls + jg * 4);
            acc2.x += bc.x; acc2.y += bc.y; acc2.z += bc.z; acc2.w += bc.w;
            *o = acc2;
        } else {
            float4 cur = *o;
            cur.x += acc2.x; cur.y += acc2.y; cur.z += acc2.z; cur.w += acc2.w;
            *o = cur;
        }
    }
}

// ---------------------------------------------------------------------------
extern "C" void kernel_launch(void* const* d_in, const int* in_sizes, int n_in,
                              void* d_out, int out_size) {
    const float* x     = (const float*)d_in[0];
    const int*   ei    = (const int*)d_in[1];     // int32 (JAX x64 off)
    const float* W_ego = (const float*)d_in[2];
    const float* b_ego = (const float*)d_in[3];
    const float* W_h1  = (const float*)d_in[4];
    const float* b_h1  = (const float*)d_in[5];
    const float* W_h2  = (const float*)d_in[6];
    const float* b_h2  = (const float*)d_in[7];
    const float* W_cls = (const float*)d_in[8];
    const float* b_cls = (const float*)d_in[9];
    float* out = (float*)d_out;

    int n = in_sizes[0] / D;        // 100000
    int E = in_sizes[1] / 2;        // 1600000
    if (E > EMAX) E = EMAX;
    const int* rows = ei;
    const int* cols = ei + E;

    float *y1, *y2, *dinv, *dinv2;
    cudaGetSymbolAddress((void**)&y1, g_y1);
    cudaGetSymbolAddress((void**)&y2, g_y2);
    cudaGetSymbolAddress((void**)&dinv, g_dinv);
    cudaGetSymbolAddress((void**)&dinv2, g_dinv2);

    const int SMEM = (128 * 128 + 64 * 132 + 128 * 16) * 4;  // 107520 B
    cudaFuncSetAttribute(gemm_branch,
                         cudaFuncAttributeMaxDynamicSharedMemorySize, SMEM);

    // CSR build
    zero_cnt<<<(n + 1023) / 1024, 1024>>>(n);
    count_kernel<<<(E + 255) / 256, 256>>>(rows, E, n);
    scan_kernel<<<1, 1024>>>(n);
    scatter_kernel<<<(E + 255) / 256, 256>>>(rows, cols, E, n);
    dinv_kernel<<<(n + 255) / 256, 256>>>(n);

    // SpMMs (gather, no atomics)
    spmm_gather<<<12800, 256>>>(x, y1, n);
    spmm_gather<<<12800, 256>>>(y1, y2, n);

    // Fused branch GEMMs
    int gb = (n + 63) / 64;
    gemm_branch<<<gb, 256, SMEM>>>(x,  nullptr, W_ego, b_ego,
                                   W_cls,              b_cls,   out, n, 1);
    gemm_branch<<<gb, 256, SMEM>>>(y1, dinv,    W_h1,  b_h1,
                                   W_cls + 128 * 16,   nullptr, out, n, 0);
    gemm_branch<<<gb, 256, SMEM>>>(y2, dinv2,   W_h2,  b_h2,
                                   W_cls + 256 * 16,   nullptr, out, n, 0);
}

// round 8
// speedup vs baseline: 2.1813x; 1.2085x over previous
#include <cuda_runtime.h>
#include <cuda_bf16.h>
#include <cstdint>

#define NMAX 100000
#define EMAX 1600000
#define D 128

// ---------------- scratch globals (no allocation allowed) -------------------
__device__ float g_y1[NMAX * D];
__device__ float g_y2[NMAX * D];
__device__ float g_dinv[NMAX];
__device__ float g_dinv2[NMAX];
__device__ int   g_cnt[NMAX];
__device__ int   g_rowptr[NMAX + 1];
__device__ int   g_cursor[NMAX];
__device__ int   g_csrcol[EMAX];
__device__ uint4 g_Whi4[3][2048];   // W hi, bf16 [k][n] row-major, 32KB each
__device__ uint4 g_Wlo4[3][2048];   // W lo

// ---------------- CSR build -------------------------------------------------
__global__ void zero_cnt(int n) {
    int i = blockIdx.x * blockDim.x + threadIdx.x;
    if (i < n) g_cnt[i] = 0;
}

__global__ void count_kernel(const int* __restrict__ rows, int E, int n) {
    int e = blockIdx.x * blockDim.x + threadIdx.x;
    if (e < E) {
        int r = rows[e];
        if ((unsigned)r < (unsigned)n) atomicAdd(&g_cnt[r], 1);
    }
}

__global__ void scan_kernel(int n) {
    __shared__ int ssum[1024];
    int tid = threadIdx.x;
    int chunk = (n + 1023) >> 10;
    int start = tid * chunk;
    int end = min(start + chunk, n);
    int local = 0;
    for (int i = start; i < end; i++) local += g_cnt[i];
    ssum[tid] = local;
    __syncthreads();
    for (int off = 1; off < 1024; off <<= 1) {
        int v = (tid >= off) ? ssum[tid - off] : 0;
        __syncthreads();
        ssum[tid] += v;
        __syncthreads();
    }
    int run = (tid == 0) ? 0 : ssum[tid - 1];
    for (int i = start; i < end; i++) {
        int c = g_cnt[i];
        g_rowptr[i] = run;
        g_cursor[i] = run;
        run += c;
    }
    if (tid == 1023) g_rowptr[n] = ssum[1023];
}

__global__ void scatter_kernel(const int* __restrict__ rows,
                               const int* __restrict__ cols, int E, int n) {
    int e = blockIdx.x * blockDim.x + threadIdx.x;
    if (e < E) {
        int r = rows[e];
        int c = cols[e];
        if ((unsigned)r < (unsigned)n && (unsigned)c < (unsigned)n) {
            int pos = atomicAdd(&g_cursor[r], 1);
            g_csrcol[pos] = c;
        }
    }
}

__global__ void dinv_kernel(int n) {
    int i = blockIdx.x * blockDim.x + threadIdx.x;
    if (i < n) {
        float d = fmaxf((float)g_cnt[i], 1.0f);
        float v = 1.0f / d;
        g_dinv[i] = v;
        g_dinv2[i] = v * v;
    }
}

// ---------------- SpMM gather (no atomics) ----------------------------------
__global__ void spmm_gather(const float* __restrict__ src,
                            float* __restrict__ dst, int n) {
    int lane = threadIdx.x & 31;
    int warp = (blockIdx.x * blockDim.x + threadIdx.x) >> 5;
    int nw = (gridDim.x * blockDim.x) >> 5;
    for (int r = warp; r < n; r += nw) {
        int s = g_rowptr[r];
        int e = g_rowptr[r + 1];
        float4 a0 = make_float4(0.f, 0.f, 0.f, 0.f);
        float4 a1 = make_float4(0.f, 0.f, 0.f, 0.f);
        float4 a2 = make_float4(0.f, 0.f, 0.f, 0.f);
        float4 a3 = make_float4(0.f, 0.f, 0.f, 0.f);
        int j = s;
        for (; j + 3 < e; j += 4) {
            int c0 = g_csrcol[j + 0];
            int c1 = g_csrcol[j + 1];
            int c2 = g_csrcol[j + 2];
            int c3 = g_csrcol[j + 3];
            float4 v0 = *reinterpret_cast<const float4*>(src + (size_t)c0 * D + lane * 4);
            float4 v1 = *reinterpret_cast<const float4*>(src + (size_t)c1 * D + lane * 4);
            float4 v2 = *reinterpret_cast<const float4*>(src + (size_t)c2 * D + lane * 4);
            float4 v3 = *reinterpret_cast<const float4*>(src + (size_t)c3 * D + lane * 4);
            a0.x += v0.x; a0.y += v0.y; a0.z += v0.z; a0.w += v0.w;
            a1.x += v1.x; a1.y += v1.y; a1.z += v1.z; a1.w += v1.w;
            a2.x += v2.x; a2.y += v2.y; a2.z += v2.z; a2.w += v2.w;
            a3.x += v3.x; a3.y += v3.y; a3.z += v3.z; a3.w += v3.w;
        }
        for (; j < e; j++) {
            int c = g_csrcol[j];
            float4 v = *reinterpret_cast<const float4*>(src + (size_t)c * D + lane * 4);
            a0.x += v.x; a0.y += v.y; a0.z += v.z; a0.w += v.w;
        }
        float4 acc;
        acc.x = (a0.x + a1.x) + (a2.x + a3.x);
        acc.y = (a0.y + a1.y) + (a2.y + a3.y);
        acc.z = (a0.z + a1.z) + (a2.z + a3.z);
        acc.w = (a0.w + a1.w) + (a2.w + a3.w);
        *reinterpret_cast<float4*>(dst + (size_t)r * D + lane * 4) = acc;
    }
}

// ---------------- W hi/lo precompute (bf16 [k][n] row-major) ----------------
__global__ void wprep_kernel(const float* __restrict__ W0,
                             const float* __restrict__ W1,
                             const float* __restrict__ W2) {
    int b = blockIdx.y;
    const float* W = (b == 0) ? W0 : ((b == 1) ? W1 : W2);
    __nv_bfloat16* hi = reinterpret_cast<__nv_bfloat16*>(g_Whi4[b]);
    __nv_bfloat16* lo = reinterpret_cast<__nv_bfloat16*>(g_Wlo4[b]);
    int idx = blockIdx.x * blockDim.x + threadIdx.x;
    if (idx < 16384) {
        float v = W[idx];
        __nv_bfloat16 h = __float2bfloat16(v);
        __nv_bfloat16 l = __float2bfloat16(v - __bfloat162float(h));
        hi[idx] = h;
        lo[idx] = l;
    }
}

// ---------------- mma.sync fused branch GEMM --------------------------------
// smem layout (bytes):
//   sAhi  [128][136] bf16 @ 0          (34816)   union: sRelu [128][133] f32
//   sAlo  [128][136] bf16 @ 34816      (34816)     (68096 <= 69632)
//   sBhi  [128][136] bf16 @ 69632      (34816)
//   sBlo  [128][136] bf16 @ 104448     (34816)
//   sWc   [128][16]  f32  @ 139264     (8192)
//   sBias [128]      f32  @ 147456     (512)
#define SM_AHI   0
#define SM_ALO   34816
#define SM_BHI   69632
#define SM_BLO   104448
#define SM_WC    139264
#define SM_BIAS  147456
#define SM_TOT   147968
#define ASTRIDE  272      // bytes per bf16 row (136 elems)

#define MMA_BF16(d, a, b) \
    asm volatile( \
        "mma.sync.aligned.m16n8k16.row.col.f32.bf16.bf16.f32 " \
        "{%0,%1,%2,%3}, {%4,%5,%6,%7}, {%8,%9}, {%0,%1,%2,%3};" \
        : "+f"((d)[0]), "+f"((d)[1]), "+f"((d)[2]), "+f"((d)[3]) \
        : "r"((a)[0]), "r"((a)[1]), "r"((a)[2]), "r"((a)[3]), \
          "r"((b)[0]), "r"((b)[1]))

#define LDSM_X4(r, addr) \
    asm volatile("ldmatrix.sync.aligned.m8n8.x4.shared.b16 {%0,%1,%2,%3}, [%4];" \
        : "=r"((r)[0]), "=r"((r)[1]), "=r"((r)[2]), "=r"((r)[3]) : "r"(addr))

#define LDSM_X4T(r, addr) \
    asm volatile("ldmatrix.sync.aligned.m8n8.x4.trans.shared.b16 {%0,%1,%2,%3}, [%4];" \
        : "=r"((r)[0]), "=r"((r)[1]), "=r"((r)[2]), "=r"((r)[3]) : "r"(addr))

__global__ void __launch_bounds__(256, 1)
gemm_mma(const float* __restrict__ A, const float* __restrict__ scale,
         const uint4* __restrict__ Whi, const uint4* __restrict__ Wlo,
         const float* __restrict__ bias, const float* __restrict__ Wc,
         const float* __restrict__ bcls, float* __restrict__ out,
         int n, int ego) {
    extern __shared__ char smc[];
    uint32_t sb;
    asm("{ .reg .u64 t; cvta.to.shared.u64 t, %1; cvt.u32.u64 %0, t; }"
        : "=r"(sb) : "l"(smc));
    int tid = threadIdx.x;
    int wid = tid >> 5;
    int lane = tid & 31;
    int rowBase = blockIdx.x * 128;

    // --- fill smem: Wc, bias, W hi/lo (padded rows), A hi/lo (padded rows) ---
    for (int i = tid; i < 512; i += 256)
        reinterpret_cast<float4*>(smc + SM_WC)[i] =
            reinterpret_cast<const float4*>(Wc)[i];
    if (tid < 128)
        reinterpret_cast<float*>(smc + SM_BIAS)[tid] = bias[tid];
    for (int i = tid; i < 2048; i += 256) {
        int k = i >> 4;           // row
        int q = i & 15;           // 16B chunk within row
        *reinterpret_cast<uint4*>(smc + SM_BHI + k * ASTRIDE + q * 16) = Whi[i];
        *reinterpret_cast<uint4*>(smc + SM_BLO + k * ASTRIDE + q * 16) = Wlo[i];
    }
    for (int i4 = tid; i4 < 4096; i4 += 256) {
        int r = i4 >> 5;
        int c4 = (i4 & 31) << 2;
        int gr = rowBase + r;
        float4 v = make_float4(0.f, 0.f, 0.f, 0.f);
        if (gr < n) {
            v = *reinterpret_cast<const float4*>(A + (size_t)gr * 128 + c4);
            if (scale) {
                float s = scale[gr];
                v.x *= s; v.y *= s; v.z *= s; v.w *= s;
            }
        }
        __nv_bfloat16 h0 = __float2bfloat16(v.x);
        __nv_bfloat16 h1 = __float2bfloat16(v.y);
        __nv_bfloat16 h2 = __float2bfloat16(v.z);
        __nv_bfloat16 h3 = __float2bfloat16(v.w);
        __nv_bfloat162 ph0; ph0.x = h0; ph0.y = h1;
        __nv_bfloat162 ph1; ph1.x = h2; ph1.y = h3;
        __nv_bfloat162 pl0;
        pl0.x = __float2bfloat16(v.x - __bfloat162float(h0));
        pl0.y = __float2bfloat16(v.y - __bfloat162float(h1));
        __nv_bfloat162 pl1;
        pl1.x = __float2bfloat16(v.z - __bfloat162float(h2));
        pl1.y = __float2bfloat16(v.w - __bfloat162float(h3));
        char* pa = smc + r * ASTRIDE + c4 * 2;
        *reinterpret_cast<__nv_bfloat162*>(pa + SM_AHI) = ph0;
        *reinterpret_cast<__nv_bfloat162*>(pa + SM_AHI + 4) = ph1;
        *reinterpret_cast<__nv_bfloat162*>(pa + SM_ALO) = pl0;
        *reinterpret_cast<__nv_bfloat162*>(pa + SM_ALO + 4) = pl1;
    }
    __syncthreads();

    // --- mainloop: warp tile = rows (wid&3)*32, cols (wid>>2)*64 ------------
    int mrow = (wid & 3) * 32;
    int ncol = (wid >> 2) * 64;

    float acc[2][8][4];
#pragma unroll
    for (int mt = 0; mt < 2; mt++)
#pragma unroll
        for (int nt = 0; nt < 8; nt++)
#pragma unroll
            for (int q = 0; q < 4; q++) acc[mt][nt][q] = 0.f;

    int arow = lane & 15;
    int acol8 = (lane >> 4) * 8;

#pragma unroll
    for (int ks = 0; ks < 8; ks++) {
        int k0 = ks * 16;
        uint32_t aHi[2][4], aLo[2][4], bHi[4][4], bLo[4][4];
#pragma unroll
        for (int mt = 0; mt < 2; mt++) {
            uint32_t ad = sb + (mrow + mt * 16 + arow) * ASTRIDE + (k0 + acol8) * 2;
            LDSM_X4(aHi[mt], ad + SM_AHI);
            LDSM_X4(aLo[mt], ad + SM_ALO);
        }
#pragma unroll
        for (int np = 0; np < 4; np++) {
            uint32_t bd = sb + (k0 + arow) * ASTRIDE + (ncol + np * 16 + acol8) * 2;
            LDSM_X4T(bHi[np], bd + SM_BHI);
            LDSM_X4T(bLo[np], bd + SM_BLO);
        }
#pragma unroll
        for (int mt = 0; mt < 2; mt++)
#pragma unroll
            for (int np = 0; np < 4; np++) {
                // n-tile pair: regs {0,1} = ntile np*2, {2,3} = ntile np*2+1
                MMA_BF16(acc[mt][np * 2],     aHi[mt], bHi[np]);
                MMA_BF16(acc[mt][np * 2],     aHi[mt], bLo[np]);
                MMA_BF16(acc[mt][np * 2],     aLo[mt], bHi[np]);
                MMA_BF16(acc[mt][np * 2 + 1], aHi[mt], (bHi[np] + 2));
                MMA_BF16(acc[mt][np * 2 + 1], aHi[mt], (bLo[np] + 2));
                MMA_BF16(acc[mt][np * 2 + 1], aLo[mt], (bHi[np] + 2));
            }
    }
    __syncthreads();   // done reading A region; reuse as relu tile

    // --- bias + relu -> sRelu [128][133] f32 (over sAhi/sAlo) --------------
    const float* sBias = reinterpret_cast<const float*>(smc + SM_BIAS);
    float* sRelu = reinterpret_cast<float*>(smc);
#pragma unroll
    for (int mt = 0; mt < 2; mt++)
#pragma unroll
        for (int nt = 0; nt < 8; nt++) {
            int col = ncol + nt * 8 + (lane & 3) * 2;
            float b0 = sBias[col], b1 = sBias[col + 1];
            int r0 = mrow + mt * 16 + (lane >> 2);
            sRelu[r0 * 133 + col]       = fmaxf(acc[mt][nt][0] + b0, 0.f);
            sRelu[r0 * 133 + col + 1]   = fmaxf(acc[mt][nt][1] + b1, 0.f);
            sRelu[(r0 + 8) * 133 + col]     = fmaxf(acc[mt][nt][2] + b0, 0.f);
            sRelu[(r0 + 8) * 133 + col + 1] = fmaxf(acc[mt][nt][3] + b1, 0.f);
        }
    __syncthreads();

    // --- classifier: row m = tid>>1, cols jg*8..+8 --------------------------
    int m = tid >> 1;
    int jg = tid & 1;
    float c8[8];
#pragma unroll
    for (int j = 0; j < 8; j++) c8[j] = 0.f;
    const char* wcBase = smc + SM_WC + jg * 32;
#pragma unroll 8
    for (int nn = 0; nn < 128; nn++) {
        float h = sRelu[m * 133 + nn];
        float4 w0 = *reinterpret_cast<const float4*>(wcBase + nn * 64);
        float4 w1 = *reinterpret_cast<const float4*>(wcBase + nn * 64 + 16);
        c8[0] += h * w0.x; c8[1] += h * w0.y; c8[2] += h * w0.z; c8[3] += h * w0.w;
        c8[4] += h * w1.x; c8[5] += h * w1.y; c8[6] += h * w1.z; c8[7] += h * w1.w;
    }
    int gr = rowBase + m;
    if (gr < n) {
        float4* o = reinterpret_cast<float4*>(out + (size_t)gr * 16 + jg * 8);
        if (ego) {
            const float4* bc = reinterpret_cast<const float4*>(bcls + jg * 8);
            float4 q0 = bc[0], q1 = bc[1];
            o[0] = make_float4(c8[0] + q0.x, c8[1] + q0.y, c8[2] + q0.z, c8[3] + q0.w);
            o[1] = make_float4(c8[4] + q1.x, c8[5] + q1.y, c8[6] + q1.z, c8[7] + q1.w);
        } else {
            float4 q0 = o[0], q1 = o[1];
            o[0] = make_float4(c8[0] + q0.x, c8[1] + q0.y, c8[2] + q0.z, c8[3] + q0.w);
            o[1] = make_float4(c8[4] + q1.x, c8[5] + q1.y, c8[6] + q1.z, c8[7] + q1.w);
        }
    }
}

// ---------------- launcher --------------------------------------------------
extern "C" void kernel_launch(void* const* d_in, const int* in_sizes, int n_in,
                              void* d_out, int out_size) {
    const float* x     = (const float*)d_in[0];
    const int*   ei    = (const int*)d_in[1];     // int32 (JAX x64 off)
    const float* W_ego = (const float*)d_in[2];
    const float* b_ego = (const float*)d_in[3];
    const float* W_h1  = (const float*)d_in[4];
    const float* b_h1  = (const float*)d_in[5];
    const float* W_h2  = (const float*)d_in[6];
    const float* b_h2  = (const float*)d_in[7];
    const float* W_cls = (const float*)d_in[8];
    const float* b_cls = (const float*)d_in[9];
    float* out = (float*)d_out;

    int n = in_sizes[0] / D;        // 100000
    int E = in_sizes[1] / 2;        // 1600000
    if (E > EMAX) E = EMAX;
    const int* rows = ei;
    const int* cols = ei + E;

    float *y1, *y2, *dinv, *dinv2;
    cudaGetSymbolAddress((void**)&y1, g_y1);
    cudaGetSymbolAddress((void**)&y2, g_y2);
    cudaGetSymbolAddress((void**)&dinv, g_dinv);
    cudaGetSymbolAddress((void**)&dinv2, g_dinv2);
    uint4 *whi, *wlo;
    cudaGetSymbolAddress((void**)&whi, g_Whi4);
    cudaGetSymbolAddress((void**)&wlo, g_Wlo4);

    cudaFuncSetAttribute(gemm_mma,
                         cudaFuncAttributeMaxDynamicSharedMemorySize, SM_TOT);

    // W prep
    wprep_kernel<<<dim3(64, 3), 256>>>(W_ego, W_h1, W_h2);

    // CSR build
    zero_cnt<<<(n + 1023) / 1024, 1024>>>(n);
    count_kernel<<<(E + 255) / 256, 256>>>(rows, E, n);
    scan_kernel<<<1, 1024>>>(n);
    scatter_kernel<<<(E + 255) / 256, 256>>>(rows, cols, E, n);
    dinv_kernel<<<(n + 255) / 256, 256>>>(n);

    // SpMMs (gather, no atomics)
    spmm_gather<<<12800, 256>>>(x, y1, n);
    spmm_gather<<<12800, 256>>>(y1, y2, n);

    // mma.sync fused branch GEMMs
    int gb = (n + 127) / 128;
    gemm_mma<<<gb, 256, SM_TOT>>>(x,  nullptr, whi,        wlo,        b_ego,
                                  W_cls,            b_cls,   out, n, 1);
    gemm_mma<<<gb, 256, SM_TOT>>>(y1, dinv,    whi + 2048, wlo + 2048, b_h1,
                                  W_cls + 128 * 16, nullptr, out, n, 0);
    gemm_mma<<<gb, 256, SM_TOT>>>(y2, dinv2,   whi + 4096, wlo + 4096, b_h2,
                                  W_cls + 256 * 16, nullptr, out, n, 0);
}

// round 9
// speedup vs baseline: 2.9752x; 1.3639x over previous
#include <cuda_runtime.h>
#include <cuda_bf16.h>
#include <cstdint>

#define NMAX 100000
#define EMAX 1600000
#define D 128

// ---------------- scratch globals (no allocation allowed) -------------------
__device__ float g_y1[NMAX * D];
__device__ float g_y2[NMAX * D];
__device__ float g_dinv[NMAX];
__device__ float g_dinv2[NMAX];
__device__ int   g_cnt[NMAX];
__device__ int   g_rowptr[NMAX + 1];
__device__ int   g_cursor[NMAX];
__device__ int   g_csrcol[EMAX];
__device__ int   g_bsum[1024];
__device__ int   g_boff[1024];
__device__ uint4 g_Whi4[3][2048];   // W hi, bf16 [k][n] row-major, 32KB each
__device__ uint4 g_Wlo4[3][2048];   // W lo

// ---------------- CSR build -------------------------------------------------
__global__ void zero_cnt(int n) {
    int i = blockIdx.x * blockDim.x + threadIdx.x;
    if (i < n) g_cnt[i] = 0;
}

__global__ void count_kernel(const int* __restrict__ rows, int E, int n) {
    int e = blockIdx.x * blockDim.x + threadIdx.x;
    if (e < E) {
        int r = rows[e];
        if ((unsigned)r < (unsigned)n) atomicAdd(&g_cnt[r], 1);
    }
}

__device__ __forceinline__ int warp_iscan(int v, int lane) {
#pragma unroll
    for (int o = 1; o < 32; o <<= 1) {
        int t = __shfl_up_sync(0xFFFFFFFFu, v, o);
        if (lane >= o) v += t;
    }
    return v;
}

// Phase A: per-block exclusive scan of g_cnt -> g_rowptr (block-local) + totals
__global__ void scan_blocks(int n) {
    __shared__ int wsum[32];
    int tid = threadIdx.x;
    int lane = tid & 31;
    int w = tid >> 5;
    int gid = blockIdx.x * 1024 + tid;
    int v = (gid < n) ? g_cnt[gid] : 0;
    int incl = warp_iscan(v, lane);
    if (lane == 31) wsum[w] = incl;
    __syncthreads();
    if (w == 0) wsum[lane] = warp_iscan(wsum[lane], lane);
    __syncthreads();
    int off = (w > 0) ? wsum[w - 1] : 0;
    if (gid < n) g_rowptr[gid] = off + incl - v;
    if (tid == 0) g_bsum[blockIdx.x] = wsum[31];
}

// Phase B: single block scans block totals; writes g_rowptr[n] = grand total
__global__ void scan_tops(int nb, int n) {
    __shared__ int wsum[32];
    int tid = threadIdx.x;
    int lane = tid & 31;
    int w = tid >> 5;
    int v = (tid < nb) ? g_bsum[tid] : 0;
    int incl = warp_iscan(v, lane);
    if (lane == 31) wsum[w] = incl;
    __syncthreads();
    if (w == 0) wsum[lane] = warp_iscan(wsum[lane], lane);
    __syncthreads();
    int off = (w > 0) ? wsum[w - 1] : 0;
    if (tid < nb) g_boff[tid] = off + incl - v;
    if (tid == 0) g_rowptr[n] = wsum[31];
}

// Phase C: add block offsets; also fused deg-inverse computation
__global__ void scan_add(int n) {
    int tid = threadIdx.x;
    int gid = blockIdx.x * 1024 + tid;
    if (gid < n) {
        int r = g_rowptr[gid] + g_boff[blockIdx.x];
        g_rowptr[gid] = r;
        g_cursor[gid] = r;
        float d = fmaxf((float)g_cnt[gid], 1.0f);
        float iv = 1.0f / d;
        g_dinv[gid] = iv;
        g_dinv2[gid] = iv * iv;
    }
}

__global__ void scatter_kernel(const int* __restrict__ rows,
                               const int* __restrict__ cols, int E, int n) {
    int e = blockIdx.x * blockDim.x + threadIdx.x;
    if (e < E) {
        int r = rows[e];
        int c = cols[e];
        if ((unsigned)r < (unsigned)n && (unsigned)c < (unsigned)n) {
            int pos = atomicAdd(&g_cursor[r], 1);
            g_csrcol[pos] = c;
        }
    }
}

// ---------------- SpMM gather (no atomics) ----------------------------------
__global__ void spmm_gather(const float* __restrict__ src,
                            float* __restrict__ dst, int n) {
    int lane = threadIdx.x & 31;
    int warp = (blockIdx.x * blockDim.x + threadIdx.x) >> 5;
    int nw = (gridDim.x * blockDim.x) >> 5;
    for (int r = warp; r < n; r += nw) {
        int s = g_rowptr[r];
        int e = g_rowptr[r + 1];
        float4 a0 = make_float4(0.f, 0.f, 0.f, 0.f);
        float4 a1 = make_float4(0.f, 0.f, 0.f, 0.f);
        float4 a2 = make_float4(0.f, 0.f, 0.f, 0.f);
        float4 a3 = make_float4(0.f, 0.f, 0.f, 0.f);
        int j = s;
        for (; j + 3 < e; j += 4) {
            int c0 = g_csrcol[j + 0];
            int c1 = g_csrcol[j + 1];
            int c2 = g_csrcol[j + 2];
            int c3 = g_csrcol[j + 3];
            float4 v0 = *reinterpret_cast<const float4*>(src + (size_t)c0 * D + lane * 4);
            float4 v1 = *reinterpret_cast<const float4*>(src + (size_t)c1 * D + lane * 4);
            float4 v2 = *reinterpret_cast<const float4*>(src + (size_t)c2 * D + lane * 4);
            float4 v3 = *reinterpret_cast<const float4*>(src + (size_t)c3 * D + lane * 4);
            a0.x += v0.x; a0.y += v0.y; a0.z += v0.z; a0.w += v0.w;
            a1.x += v1.x; a1.y += v1.y; a1.z += v1.z; a1.w += v1.w;
            a2.x += v2.x; a2.y += v2.y; a2.z += v2.z; a2.w += v2.w;
            a3.x += v3.x; a3.y += v3.y; a3.z += v3.z; a3.w += v3.w;
        }
        for (; j < e; j++) {
            int c = g_csrcol[j];
            float4 v = *reinterpret_cast<const float4*>(src + (size_t)c * D + lane * 4);
            a0.x += v.x; a0.y += v.y; a0.z += v.z; a0.w += v.w;
        }
        float4 acc;
        acc.x = (a0.x + a1.x) + (a2.x + a3.x);
        acc.y = (a0.y + a1.y) + (a2.y + a3.y);
        acc.z = (a0.z + a1.z) + (a2.z + a3.z);
        acc.w = (a0.w + a1.w) + (a2.w + a3.w);
        *reinterpret_cast<float4*>(dst + (size_t)r * D + lane * 4) = acc;
    }
}

// ---------------- W hi/lo precompute (bf16 [k][n] row-major) ----------------
__global__ void wprep_kernel(const float* __restrict__ W0,
                             const float* __restrict__ W1,
                             const float* __restrict__ W2) {
    int b = blockIdx.y;
    const float* W = (b == 0) ? W0 : ((b == 1) ? W1 : W2);
    __nv_bfloat16* hi = reinterpret_cast<__nv_bfloat16*>(g_Whi4[b]);
    __nv_bfloat16* lo = reinterpret_cast<__nv_bfloat16*>(g_Wlo4[b]);
    int idx = blockIdx.x * blockDim.x + threadIdx.x;
    if (idx < 16384) {
        float v = W[idx];
        __nv_bfloat16 h = __float2bfloat16(v);
        __nv_bfloat16 l = __float2bfloat16(v - __bfloat162float(h));
        hi[idx] = h;
        lo[idx] = l;
    }
}

// ---------------- mma.sync fused branch GEMM --------------------------------
#define SM_AHI   0
#define SM_ALO   34816
#define SM_BHI   69632
#define SM_BLO   104448
#define SM_WC    139264
#define SM_BIAS  147456
#define SM_TOT   147968
#define ASTRIDE  272      // bytes per bf16 row (136 elems)

#define MMA_BF16(d, a, b) \
    asm volatile( \
        "mma.sync.aligned.m16n8k16.row.col.f32.bf16.bf16.f32 " \
        "{%0,%1,%2,%3}, {%4,%5,%6,%7}, {%8,%9}, {%0,%1,%2,%3};" \
        : "+f"((d)[0]), "+f"((d)[1]), "+f"((d)[2]), "+f"((d)[3]) \
        : "r"((a)[0]), "r"((a)[1]), "r"((a)[2]), "r"((a)[3]), \
          "r"((b)[0]), "r"((b)[1]))

#define LDSM_X4(r, addr) \
    asm volatile("ldmatrix.sync.aligned.m8n8.x4.shared.b16 {%0,%1,%2,%3}, [%4];" \
        : "=r"((r)[0]), "=r"((r)[1]), "=r"((r)[2]), "=r"((r)[3]) : "r"(addr))

#define LDSM_X4T(r, addr) \
    asm volatile("ldmatrix.sync.aligned.m8n8.x4.trans.shared.b16 {%0,%1,%2,%3}, [%4];" \
        : "=r"((r)[0]), "=r"((r)[1]), "=r"((r)[2]), "=r"((r)[3]) : "r"(addr))

__global__ void __launch_bounds__(256, 1)
gemm_mma(const float* __restrict__ A, const float* __restrict__ scale,
         const uint4* __restrict__ Whi, const uint4* __restrict__ Wlo,
         const float* __restrict__ bias, const float* __restrict__ Wc,
         const float* __restrict__ bcls, float* __restrict__ out,
         int n, int ego) {
    extern __shared__ char smc[];
    uint32_t sb;
    asm("{ .reg .u64 t; cvta.to.shared.u64 t, %1; cvt.u32.u64 %0, t; }"
        : "=r"(sb) : "l"(smc));
    int tid = threadIdx.x;
    int wid = tid >> 5;
    int lane = tid & 31;
    int rowBase = blockIdx.x * 128;

    for (int i = tid; i < 512; i += 256)
        reinterpret_cast<float4*>(smc + SM_WC)[i] =
            reinterpret_cast<const float4*>(Wc)[i];
    if (tid < 128)
        reinterpret_cast<float*>(smc + SM_BIAS)[tid] = bias[tid];
    for (int i = tid; i < 2048; i += 256) {
        int k = i >> 4;
        int q = i & 15;
        *reinterpret_cast<uint4*>(smc + SM_BHI + k * ASTRIDE + q * 16) = Whi[i];
        *reinterpret_cast<uint4*>(smc + SM_BLO + k * ASTRIDE + q * 16) = Wlo[i];
    }
    for (int i4 = tid; i4 < 4096; i4 += 256) {
        int r = i4 >> 5;
        int c4 = (i4 & 31) << 2;
        int gr = rowBase + r;
        float4 v = make_float4(0.f, 0.f, 0.f, 0.f);
        if (gr < n) {
            v = *reinterpret_cast<const float4*>(A + (size_t)gr * 128 + c4);
            if (scale) {
                float s = scale[gr];
                v.x *= s; v.y *= s; v.z *= s; v.w *= s;
            }
        }
        __nv_bfloat16 h0 = __float2bfloat16(v.x);
        __nv_bfloat16 h1 = __float2bfloat16(v.y);
        __nv_bfloat16 h2 = __float2bfloat16(v.z);
        __nv_bfloat16 h3 = __float2bfloat16(v.w);
        __nv_bfloat162 ph0; ph0.x = h0; ph0.y = h1;
        __nv_bfloat162 ph1; ph1.x = h2; ph1.y = h3;
        __nv_bfloat162 pl0;
        pl0.x = __float2bfloat16(v.x - __bfloat162float(h0));
        pl0.y = __float2bfloat16(v.y - __bfloat162float(h1));
        __nv_bfloat162 pl1;
        pl1.x = __float2bfloat16(v.z - __bfloat162float(h2));
        pl1.y = __float2bfloat16(v.w - __bfloat162float(h3));
        char* pa = smc + r * ASTRIDE + c4 * 2;
        *reinterpret_cast<__nv_bfloat162*>(pa + SM_AHI) = ph0;
        *reinterpret_cast<__nv_bfloat162*>(pa + SM_AHI + 4) = ph1;
        *reinterpret_cast<__nv_bfloat162*>(pa + SM_ALO) = pl0;
        *reinterpret_cast<__nv_bfloat162*>(pa + SM_ALO + 4) = pl1;
    }
    __syncthreads();

    int mrow = (wid & 3) * 32;
    int ncol = (wid >> 2) * 64;

    float acc[2][8][4];
#pragma unroll
    for (int mt = 0; mt < 2; mt++)
#pragma unroll
        for (int nt = 0; nt < 8; nt++)
#pragma unroll
            for (int q = 0; q < 4; q++) acc[mt][nt][q] = 0.f;

    int arow = lane & 15;
    int acol8 = (lane >> 4) * 8;

#pragma unroll
    for (int ks = 0; ks < 8; ks++) {
        int k0 = ks * 16;
        uint32_t aHi[2][4], aLo[2][4], bHi[4][4], bLo[4][4];
#pragma unroll
        for (int mt = 0; mt < 2; mt++) {
            uint32_t ad = sb + (mrow + mt * 16 + arow) * ASTRIDE + (k0 + acol8) * 2;
            LDSM_X4(aHi[mt], ad + SM_AHI);
            LDSM_X4(aLo[mt], ad + SM_ALO);
        }
#pragma unroll
        for (int np = 0; np < 4; np++) {
            uint32_t bd = sb + (k0 + arow) * ASTRIDE + (ncol + np * 16 + acol8) * 2;
            LDSM_X4T(bHi[np], bd + SM_BHI);
            LDSM_X4T(bLo[np], bd + SM_BLO);
        }
#pragma unroll
        for (int mt = 0; mt < 2; mt++)
#pragma unroll
            for (int np = 0; np < 4; np++) {
                MMA_BF16(acc[mt][np * 2],     aHi[mt], bHi[np]);
                MMA_BF16(acc[mt][np * 2],     aHi[mt], bLo[np]);
                MMA_BF16(acc[mt][np * 2],     aLo[mt], bHi[np]);
                MMA_BF16(acc[mt][np * 2 + 1], aHi[mt], (bHi[np] + 2));
                MMA_BF16(acc[mt][np * 2 + 1], aHi[mt], (bLo[np] + 2));
                MMA_BF16(acc[mt][np * 2 + 1], aLo[mt], (bHi[np] + 2));
            }
    }
    __syncthreads();

    const float* sBias = reinterpret_cast<const float*>(smc + SM_BIAS);
    float* sRelu = reinterpret_cast<float*>(smc);
#pragma unroll
    for (int mt = 0; mt < 2; mt++)
#pragma unroll
        for (int nt = 0; nt < 8; nt++) {
            int col = ncol + nt * 8 + (lane & 3) * 2;
            float b0 = sBias[col], b1 = sBias[col + 1];
            int r0 = mrow + mt * 16 + (lane >> 2);
            sRelu[r0 * 133 + col]       = fmaxf(acc[mt][nt][0] + b0, 0.f);
            sRelu[r0 * 133 + col + 1]   = fmaxf(acc[mt][nt][1] + b1, 0.f);
            sRelu[(r0 + 8) * 133 + col]     = fmaxf(acc[mt][nt][2] + b0, 0.f);
            sRelu[(r0 + 8) * 133 + col + 1] = fmaxf(acc[mt][nt][3] + b1, 0.f);
        }
    __syncthreads();

    int m = tid >> 1;
    int jg = tid & 1;
    float c8[8];
#pragma unroll
    for (int j = 0; j < 8; j++) c8[j] = 0.f;
    const char* wcBase = smc + SM_WC + jg * 32;
#pragma unroll 8
    for (int nn = 0; nn < 128; nn++) {
        float h = sRelu[m * 133 + nn];
        float4 w0 = *reinterpret_cast<const float4*>(wcBase + nn * 64);
        float4 w1 = *reinterpret_cast<const float4*>(wcBase + nn * 64 + 16);
        c8[0] += h * w0.x; c8[1] += h * w0.y; c8[2] += h * w0.z; c8[3] += h * w0.w;
        c8[4] += h * w1.x; c8[5] += h * w1.y; c8[6] += h * w1.z; c8[7] += h * w1.w;
    }
    int gr = rowBase + m;
    if (gr < n) {
        float4* o = reinterpret_cast<float4*>(out + (size_t)gr * 16 + jg * 8);
        if (ego) {
            const float4* bc = reinterpret_cast<const float4*>(bcls + jg * 8);
            float4 q0 = bc[0], q1 = bc[1];
            o[0] = make_float4(c8[0] + q0.x, c8[1] + q0.y, c8[2] + q0.z, c8[3] + q0.w);
            o[1] = make_float4(c8[4] + q1.x, c8[5] + q1.y, c8[6] + q1.z, c8[7] + q1.w);
        } else {
            float4 q0 = o[0], q1 = o[1];
            o[0] = make_float4(c8[0] + q0.x, c8[1] + q0.y, c8[2] + q0.z, c8[3] + q0.w);
            o[1] = make_float4(c8[4] + q1.x, c8[5] + q1.y, c8[6] + q1.z, c8[7] + q1.w);
        }
    }
}

// ---------------- launcher --------------------------------------------------
extern "C" void kernel_launch(void* const* d_in, const int* in_sizes, int n_in,
                              void* d_out, int out_size) {
    const float* x     = (const float*)d_in[0];
    const int*   ei    = (const int*)d_in[1];     // int32 (JAX x64 off)
    const float* W_ego = (const float*)d_in[2];
    const float* b_ego = (const float*)d_in[3];
    const float* W_h1  = (const float*)d_in[4];
    const float* b_h1  = (const float*)d_in[5];
    const float* W_h2  = (const float*)d_in[6];
    const float* b_h2  = (const float*)d_in[7];
    const float* W_cls = (const float*)d_in[8];
    const float* b_cls = (const float*)d_in[9];
    float* out = (float*)d_out;

    int n = in_sizes[0] / D;        // 100000
    int E = in_sizes[1] / 2;        // 1600000
    if (E > EMAX) E = EMAX;
    const int* rows = ei;
    const int* cols = ei + E;

    float *y1, *y2, *dinv, *dinv2;
    cudaGetSymbolAddress((void**)&y1, g_y1);
    cudaGetSymbolAddress((void**)&y2, g_y2);
    cudaGetSymbolAddress((void**)&dinv, g_dinv);
    cudaGetSymbolAddress((void**)&dinv2, g_dinv2);
    uint4 *whi, *wlo;
    cudaGetSymbolAddress((void**)&whi, g_Whi4);
    cudaGetSymbolAddress((void**)&wlo, g_Wlo4);

    cudaFuncSetAttribute(gemm_mma,
                         cudaFuncAttributeMaxDynamicSharedMemorySize, SM_TOT);

    // W prep
    wprep_kernel<<<dim3(64, 3), 256>>>(W_ego, W_h1, W_h2);

    // CSR build (parallel 3-phase scan; dinv fused into phase C)
    int nb = (n + 1023) / 1024;     // 98
    zero_cnt<<<nb, 1024>>>(n);
    count_kernel<<<(E + 255) / 256, 256>>>(rows, E, n);
    scan_blocks<<<nb, 1024>>>(n);
    scan_tops<<<1, 1024>>>(nb, n);
    scan_add<<<nb, 1024>>>(n);
    scatter_kernel<<<(E + 255) / 256, 256>>>(rows, cols, E, n);

    // SpMMs (gather, no atomics)
    spmm_gather<<<12800, 256>>>(x, y1, n);
    spmm_gather<<<12800, 256>>>(y1, y2, n);

    // mma.sync fused branch GEMMs
    int gb = (n + 127) / 128;
    gemm_mma<<<gb, 256, SM_TOT>>>(x,  nullptr, whi,        wlo,        b_ego,
                                  W_cls,            b_cls,   out, n, 1);
    gemm_mma<<<gb, 256, SM_TOT>>>(y1, dinv,    whi + 2048, wlo + 2048, b_h1,
                                  W_cls + 128 * 16, nullptr, out, n, 0);
    gemm_mma<<<gb, 256, SM_TOT>>>(y2, dinv2,   whi + 4096, wlo + 4096, b_h2,
                                  W_cls + 256 * 16, nullptr, out, n, 0);
}

// round 13
// speedup vs baseline: 3.0346x; 1.0200x over previous
#include <cuda_runtime.h>
#include <cuda_bf16.h>
#include <cstdint>

#define NMAX 100000
#define EMAX 1600000
#define D 128

// ---------------- scratch globals (no allocation allowed) -------------------
__device__ float g_y1[NMAX * D];
__device__ float g_y2[NMAX * D];
__device__ float g_dinv[NMAX];
__device__ float g_dinv2[NMAX];
__device__ int   g_cnt[NMAX];
__device__ int   g_rowptr[NMAX + 1];
__device__ int   g_cursor[NMAX];
__device__ int   g_csrcol[EMAX];
__device__ int   g_bsum[1024];
__device__ int   g_boff[1024];
__device__ uint4 g_Whi4[3][2048];   // W hi, bf16 [k][n] row-major, 32KB each
__device__ uint4 g_Wlo4[3][2048];   // W lo

// ---------------- CSR build -------------------------------------------------
__global__ void zero_cnt(int n) {
    int i = blockIdx.x * blockDim.x + threadIdx.x;
    if (i < n) g_cnt[i] = 0;
}

__global__ void count_kernel(const int* __restrict__ rows, int E, int n) {
    int e = blockIdx.x * blockDim.x + threadIdx.x;
    if (e < E) {
        int r = rows[e];
        if ((unsigned)r < (unsigned)n) atomicAdd(&g_cnt[r], 1);
    }
}

__device__ __forceinline__ int warp_iscan(int v, int lane) {
#pragma unroll
    for (int o = 1; o < 32; o <<= 1) {
        int t = __shfl_up_sync(0xFFFFFFFFu, v, o);
        if (lane >= o) v += t;
    }
    return v;
}

__global__ void scan_blocks(int n) {
    __shared__ int wsum[32];
    int tid = threadIdx.x;
    int lane = tid & 31;
    int w = tid >> 5;
    int gid = blockIdx.x * 1024 + tid;
    int v = (gid < n) ? g_cnt[gid] : 0;
    int incl = warp_iscan(v, lane);
    if (lane == 31) wsum[w] = incl;
    __syncthreads();
    if (w == 0) wsum[lane] = warp_iscan(wsum[lane], lane);
    __syncthreads();
    int off = (w > 0) ? wsum[w - 1] : 0;
    if (gid < n) g_rowptr[gid] = off + incl - v;
    if (tid == 0) g_bsum[blockIdx.x] = wsum[31];
}

__global__ void scan_tops(int nb, int n) {
    __shared__ int wsum[32];
    int tid = threadIdx.x;
    int lane = tid & 31;
    int w = tid >> 5;
    int v = (tid < nb) ? g_bsum[tid] : 0;
    int incl = warp_iscan(v, lane);
    if (lane == 31) wsum[w] = incl;
    __syncthreads();
    if (w == 0) wsum[lane] = warp_iscan(wsum[lane], lane);
    __syncthreads();
    int off = (w > 0) ? wsum[w - 1] : 0;
    if (tid < nb) g_boff[tid] = off + incl - v;
    if (tid == 0) g_rowptr[n] = wsum[31];
}

__global__ void scan_add(int n) {
    int tid = threadIdx.x;
    int gid = blockIdx.x * 1024 + tid;
    if (gid < n) {
        int r = g_rowptr[gid] + g_boff[blockIdx.x];
        g_rowptr[gid] = r;
        g_cursor[gid] = r;
        float d = fmaxf((float)g_cnt[gid], 1.0f);
        float iv = 1.0f / d;
        g_dinv[gid] = iv;
        g_dinv2[gid] = iv * iv;
    }
}

__global__ void scatter_kernel(const int* __restrict__ rows,
                               const int* __restrict__ cols, int E, int n) {
    int e = blockIdx.x * blockDim.x + threadIdx.x;
    if (e < E) {
        int r = rows[e];
        int c = cols[e];
        if ((unsigned)r < (unsigned)n && (unsigned)c < (unsigned)n) {
            int pos = atomicAdd(&g_cursor[r], 1);
            g_csrcol[pos] = c;
        }
    }
}

// ---------------- SpMM gather (no atomics) ----------------------------------
__global__ void spmm_gather(const float* __restrict__ src,
                            float* __restrict__ dst, int n) {
    int lane = threadIdx.x & 31;
    int warp = (blockIdx.x * blockDim.x + threadIdx.x) >> 5;
    int nw = (gridDim.x * blockDim.x) >> 5;
    for (int r = warp; r < n; r += nw) {
        int s = g_rowptr[r];
        int e = g_rowptr[r + 1];
        float4 a0 = make_float4(0.f, 0.f, 0.f, 0.f);
        float4 a1 = make_float4(0.f, 0.f, 0.f, 0.f);
        float4 a2 = make_float4(0.f, 0.f, 0.f, 0.f);
        float4 a3 = make_float4(0.f, 0.f, 0.f, 0.f);
        int j = s;
        for (; j + 3 < e; j += 4) {
            int c0 = g_csrcol[j + 0];
            int c1 = g_csrcol[j + 1];
            int c2 = g_csrcol[j + 2];
            int c3 = g_csrcol[j + 3];
            float4 v0 = *reinterpret_cast<const float4*>(src + (size_t)c0 * D + lane * 4);
            float4 v1 = *reinterpret_cast<const float4*>(src + (size_t)c1 * D + lane * 4);
            float4 v2 = *reinterpret_cast<const float4*>(src + (size_t)c2 * D + lane * 4);
            float4 v3 = *reinterpret_cast<const float4*>(src + (size_t)c3 * D + lane * 4);
            a0.x += v0.x; a0.y += v0.y; a0.z += v0.z; a0.w += v0.w;
            a1.x += v1.x; a1.y += v1.y; a1.z += v1.z; a1.w += v1.w;
            a2.x += v2.x; a2.y += v2.y; a2.z += v2.z; a2.w += v2.w;
            a3.x += v3.x; a3.y += v3.y; a3.z += v3.z; a3.w += v3.w;
        }
        for (; j < e; j++) {
            int c = g_csrcol[j];
            float4 v = *reinterpret_cast<const float4*>(src + (size_t)c * D + lane * 4);
            a0.x += v.x; a0.y += v.y; a0.z += v.z; a0.w += v.w;
        }
        float4 acc;
        acc.x = (a0.x + a1.x) + (a2.x + a3.x);
        acc.y = (a0.y + a1.y) + (a2.y + a3.y);
        acc.z = (a0.z + a1.z) + (a2.z + a3.z);
        acc.w = (a0.w + a1.w) + (a2.w + a3.w);
        *reinterpret_cast<float4*>(dst + (size_t)r * D + lane * 4) = acc;
    }
}

// ---------------- W hi/lo precompute (bf16 [k][n] row-major) ----------------
__global__ void wprep_kernel(const float* __restrict__ W0,
                             const float* __restrict__ W1,
                             const float* __restrict__ W2) {
    int b = blockIdx.y;
    const float* W = (b == 0) ? W0 : ((b == 1) ? W1 : W2);
    __nv_bfloat16* hi = reinterpret_cast<__nv_bfloat16*>(g_Whi4[b]);
    __nv_bfloat16* lo = reinterpret_cast<__nv_bfloat16*>(g_Wlo4[b]);
    int idx = blockIdx.x * blockDim.x + threadIdx.x;
    if (idx < 16384) {
        float v = W[idx];
        __nv_bfloat16 h = __float2bfloat16(v);
        __nv_bfloat16 l = __float2bfloat16(v - __bfloat162float(h));
        hi[idx] = h;
        lo[idx] = l;
    }
}

// ---------------- out init: broadcast b_cls ---------------------------------
__global__ void init_out(float* __restrict__ out, const float* __restrict__ bcls,
                         int n) {
    __shared__ float bc[16];
    if (threadIdx.x < 16) bc[threadIdx.x] = bcls[threadIdx.x];
    __syncthreads();
    int i = blockIdx.x * blockDim.x + threadIdx.x;
    if (i < n * 16) out[i] = bc[i & 15];
}

// ---------------- merged mma.sync fused branch GEMM -------------------------
#define SM_AHI   0
#define SM_ALO   34816
#define SM_BHI   69632
#define SM_BLO   104448
#define SM_WC    139264
#define SM_BIAS  147456
#define SM_TOT   147968
#define ASTRIDE  272      // bytes per bf16 row (136 elems)

#define MMA_BF16(d, a, b) \
    asm volatile( \
        "mma.sync.aligned.m16n8k16.row.col.f32.bf16.bf16.f32 " \
        "{%0,%1,%2,%3}, {%4,%5,%6,%7}, {%8,%9}, {%0,%1,%2,%3};" \
        : "+f"((d)[0]), "+f"((d)[1]), "+f"((d)[2]), "+f"((d)[3]) \
        : "r"((a)[0]), "r"((a)[1]), "r"((a)[2]), "r"((a)[3]), \
          "r"((b)[0]), "r"((b)[1]))

#define LDSM_X4(r, addr) \
    asm volatile("ldmatrix.sync.aligned.m8n8.x4.shared.b16 {%0,%1,%2,%3}, [%4];" \
        : "=r"((r)[0]), "=r"((r)[1]), "=r"((r)[2]), "=r"((r)[3]) : "r"(addr))

#define LDSM_X4T(r, addr) \
    asm volatile("ldmatrix.sync.aligned.m8n8.x4.trans.shared.b16 {%0,%1,%2,%3}, [%4];" \
        : "=r"((r)[0]), "=r"((r)[1]), "=r"((r)[2]), "=r"((r)[3]) : "r"(addr))

__global__ void __launch_bounds__(256, 1)
gemm_mma(const float* __restrict__ A0, const float* __restrict__ A1,
         const float* __restrict__ A2,
         const float* __restrict__ bias0, const float* __restrict__ bias1,
         const float* __restrict__ bias2,
         const float* __restrict__ Wcls, float* __restrict__ out, int n) {
    extern __shared__ char smc[];
    uint32_t sb;
    asm("{ .reg .u64 t; cvta.to.shared.u64 t, %1; cvt.u32.u64 %0, t; }"
        : "=r"(sb) : "l"(smc));
    int tid = threadIdx.x;
    int wid = tid >> 5;
    int lane = tid & 31;
    int rowBase = blockIdx.x * 128;
    int br = blockIdx.y;          // branch 0=ego 1=h1 2=h2

    const float* A    = (br == 0) ? A0 : ((br == 1) ? A1 : A2);
    const float* bias = (br == 0) ? bias0 : ((br == 1) ? bias1 : bias2);
    const float* scale = (br == 0) ? nullptr : ((br == 1) ? g_dinv : g_dinv2);
    const uint4* Whi = g_Whi4[br];
    const uint4* Wlo = g_Wlo4[br];
    const float* Wc = Wcls + br * 128 * 16;

    for (int i = tid; i < 512; i += 256)
        reinterpret_cast<float4*>(smc + SM_WC)[i] =
            reinterpret_cast<const float4*>(Wc)[i];
    if (tid < 128)
        reinterpret_cast<float*>(smc + SM_BIAS)[tid] = bias[tid];
    for (int i = tid; i < 2048; i += 256) {
        int k = i >> 4;
        int q = i & 15;
        *reinterpret_cast<uint4*>(smc + SM_BHI + k * ASTRIDE + q * 16) = Whi[i];
        *reinterpret_cast<uint4*>(smc + SM_BLO + k * ASTRIDE + q * 16) = Wlo[i];
    }
    for (int i4 = tid; i4 < 4096; i4 += 256) {
        int r = i4 >> 5;
        int c4 = (i4 & 31) << 2;
        int gr = rowBase + r;
        float4 v = make_float4(0.f, 0.f, 0.f, 0.f);
        if (gr < n) {
            v = *reinterpret_cast<const float4*>(A + (size_t)gr * 128 + c4);
            if (scale) {
                float s = scale[gr];
                v.x *= s; v.y *= s; v.z *= s; v.w *= s;
            }
        }
        __nv_bfloat16 h0 = __float2bfloat16(v.x);
        __nv_bfloat16 h1 = __float2bfloat16(v.y);
        __nv_bfloat16 h2 = __float2bfloat16(v.z);
        __nv_bfloat16 h3 = __float2bfloat16(v.w);
        __nv_bfloat162 ph0; ph0.x = h0; ph0.y = h1;
        __nv_bfloat162 ph1; ph1.x = h2; ph1.y = h3;
        __nv_bfloat162 pl0;
        pl0.x = __float2bfloat16(v.x - __bfloat162float(h0));
        pl0.y = __float2bfloat16(v.y - __bfloat162float(h1));
        __nv_bfloat162 pl1;
        pl1.x = __float2bfloat16(v.z - __bfloat162float(h2));
        pl1.y = __float2bfloat16(v.w - __bfloat162float(h3));
        char* pa = smc + r * ASTRIDE + c4 * 2;
        *reinterpret_cast<__nv_bfloat162*>(pa + SM_AHI) = ph0;
        *reinterpret_cast<__nv_bfloat162*>(pa + SM_AHI + 4) = ph1;
        *reinterpret_cast<__nv_bfloat162*>(pa + SM_ALO) = pl0;
        *reinterpret_cast<__nv_bfloat162*>(pa + SM_ALO + 4) = pl1;
    }
    __syncthreads();

    int mrow = (wid & 3) * 32;
    int ncol = (wid >> 2) * 64;

    float acc[2][8][4];
#pragma unroll
    for (int mt = 0; mt < 2; mt++)
#pragma unroll
        for (int nt = 0; nt < 8; nt++)
#pragma unroll
            for (int q = 0; q < 4; q++) acc[mt][nt][q] = 0.f;

    int arow = lane & 15;
    int acol8 = (lane >> 4) * 8;

#pragma unroll
    for (int ks = 0; ks < 8; ks++) {
        int k0 = ks * 16;
        uint32_t aHi[2][4], aLo[2][4], bHi[4][4], bLo[4][4];
#pragma unroll
        for (int mt = 0; mt < 2; mt++) {
            uint32_t ad = sb + (mrow + mt * 16 + arow) * ASTRIDE + (k0 + acol8) * 2;
            LDSM_X4(aHi[mt], ad + SM_AHI);
            LDSM_X4(aLo[mt], ad + SM_ALO);
        }
#pragma unroll
        for (int np = 0; np < 4; np++) {
            uint32_t bd = sb + (k0 + arow) * ASTRIDE + (ncol + np * 16 + acol8) * 2;
            LDSM_X4T(bHi[np], bd + SM_BHI);
            LDSM_X4T(bLo[np], bd + SM_BLO);
        }
#pragma unroll
        for (int mt = 0; mt < 2; mt++)
#pragma unroll
            for (int np = 0; np < 4; np++) {
                MMA_BF16(acc[mt][np * 2],     aHi[mt], bHi[np]);
                MMA_BF16(acc[mt][np * 2],     aHi[mt], bLo[np]);
                MMA_BF16(acc[mt][np * 2],     aLo[mt], bHi[np]);
                MMA_BF16(acc[mt][np * 2 + 1], aHi[mt], (bHi[np] + 2));
                MMA_BF16(acc[mt][np * 2 + 1], aHi[mt], (bLo[np] + 2));
                MMA_BF16(acc[mt][np * 2 + 1], aLo[mt], (bHi[np] + 2));
            }
    }
    __syncthreads();

    const float* sBias = reinterpret_cast<const float*>(smc + SM_BIAS);
    float* sRelu = reinterpret_cast<float*>(smc);
#pragma unroll
    for (int mt = 0; mt < 2; mt++)
#pragma unroll
        for (int nt = 0; nt < 8; nt++) {
            int col = ncol + nt * 8 + (lane & 3) * 2;
            float b0 = sBias[col], b1 = sBias[col + 1];
            int r0 = mrow + mt * 16 + (lane >> 2);
            sRelu[r0 * 133 + col]       = fmaxf(acc[mt][nt][0] + b0, 0.f);
            sRelu[r0 * 133 + col + 1]   = fmaxf(acc[mt][nt][1] + b1, 0.f);
            sRelu[(r0 + 8) * 133 + col]     = fmaxf(acc[mt][nt][2] + b0, 0.f);
            sRelu[(r0 + 8) * 133 + col + 1] = fmaxf(acc[mt][nt][3] + b1, 0.f);
        }
    __syncthreads();

    int m = tid >> 1;
    int jg = tid & 1;
    float c8[8];
#pragma unroll
    for (int j = 0; j < 8; j++) c8[j] = 0.f;
    const char* wcBase = smc + SM_WC + jg * 32;
#pragma unroll 8
    for (int nn = 0; nn < 128; nn++) {
        float h = sRelu[m * 133 + nn];
        float4 w0 = *reinterpret_cast<const float4*>(wcBase + nn * 64);
        float4 w1 = *reinterpret_cast<const float4*>(wcBase + nn * 64 + 16);
        c8[0] += h * w0.x; c8[1] += h * w0.y; c8[2] += h * w0.z; c8[3] += h * w0.w;
        c8[4] += h * w1.x; c8[5] += h * w1.y; c8[6] += h * w1.z; c8[7] += h * w1.w;
    }
    int gr = rowBase + m;
    if (gr < n) {
        float* o = out + (size_t)gr * 16 + jg * 8;
#pragma unroll
        for (int j = 0; j < 8; j++) atomicAdd(o + j, c8[j]);
    }
}

// ---------------- launcher --------------------------------------------------
extern "C" void kernel_launch(void* const* d_in, const int* in_sizes, int n_in,
                              void* d_out, int out_size) {
    const float* x     = (const float*)d_in[0];
    const int*   ei    = (const int*)d_in[1];     // int32 (JAX x64 off)
    const float* W_ego = (const float*)d_in[2];
    const float* b_ego = (const float*)d_in[3];
    const float* W_h1  = (const float*)d_in[4];
    const float* b_h1  = (const float*)d_in[5];
    const float* W_h2  = (const float*)d_in[6];
    const float* b_h2  = (const float*)d_in[7];
    const float* W_cls = (const float*)d_in[8];
    const float* b_cls = (const float*)d_in[9];
    float* out = (float*)d_out;

    int n = in_sizes[0] / D;        // 100000
    int E = in_sizes[1] / 2;        // 1600000
    if (E > EMAX) E = EMAX;
    const int* rows = ei;
    const int* cols = ei + E;

    float *y1, *y2;
    cudaGetSymbolAddress((void**)&y1, g_y1);
    cudaGetSymbolAddress((void**)&y2, g_y2);

    cudaFuncSetAttribute(gemm_mma,
                         cudaFuncAttributeMaxDynamicSharedMemorySize, SM_TOT);

    // W prep + out init (independent of CSR)
    wprep_kernel<<<dim3(64, 3), 256>>>(W_ego, W_h1, W_h2);
    init_out<<<(n * 16 + 255) / 256, 256>>>(out, b_cls, n);

    // CSR build (parallel 3-phase scan; dinv fused into phase C)
    int nb = (n + 1023) / 1024;     // 98
    zero_cnt<<<nb, 1024>>>(n);
    count_kernel<<<(E + 255) / 256, 256>>>(rows, E, n);
    scan_blocks<<<nb, 1024>>>(n);
    scan_tops<<<1, 1024>>>(nb, n);
    scan_add<<<nb, 1024>>>(n);
    scatter_kernel<<<(E + 255) / 256, 256>>>(rows, cols, E, n);

    // SpMMs (gather, no atomics)
    spmm_gather<<<12800, 256>>>(x, y1, n);
    spmm_gather<<<12800, 256>>>(y1, y2, n);

    // ONE merged gemm launch: grid (tiles, 3 branches)
    int gb = (n + 127) / 128;
    gemm_mma<<<dim3(gb, 3), 256, SM_TOT>>>(x, y1, y2, b_ego, b_h1, b_h2,
                                           W_cls, out, n);
}

// round 16
// speedup vs baseline: 3.1169x; 1.0271x over previous
#include <cuda_runtime.h>
#include <cuda_bf16.h>
#include <cstdint>

#define NMAX 100000
#define EMAX 1600000
#define D 128

// ---------------- scratch globals (no allocation allowed) -------------------
__device__ float g_y1[NMAX * D];
__device__ float g_y2[NMAX * D];
__device__ float g_dinv[NMAX];
__device__ float g_dinv2[NMAX];
__device__ int   g_cnt[NMAX];
__device__ int   g_rowptr[NMAX + 1];
__device__ int   g_cursor[NMAX];
__device__ int   g_csrcol[EMAX];
__device__ int   g_bsum[1024];
__device__ int   g_boff[1024];
__device__ uint4 g_Whi4[3][2048];   // W hi, bf16 [k][n] row-major, 32KB each
__device__ uint4 g_Wlo4[3][2048];   // W lo

// ---------------- CSR build -------------------------------------------------
__global__ void zero_cnt(int n) {
    int i = blockIdx.x * blockDim.x + threadIdx.x;
    if (i < n) g_cnt[i] = 0;
}

__global__ void count_kernel(const int* __restrict__ rows, int E, int n) {
    int e = blockIdx.x * blockDim.x + threadIdx.x;
    if (e < E) {
        int r = rows[e];
        if ((unsigned)r < (unsigned)n) atomicAdd(&g_cnt[r], 1);
    }
}

__device__ __forceinline__ int warp_iscan(int v, int lane) {
#pragma unroll
    for (int o = 1; o < 32; o <<= 1) {
        int t = __shfl_up_sync(0xFFFFFFFFu, v, o);
        if (lane >= o) v += t;
    }
    return v;
}

__global__ void scan_blocks(int n) {
    __shared__ int wsum[32];
    int tid = threadIdx.x;
    int lane = tid & 31;
    int w = tid >> 5;
    int gid = blockIdx.x * 1024 + tid;
    int v = (gid < n) ? g_cnt[gid] : 0;
    int incl = warp_iscan(v, lane);
    if (lane == 31) wsum[w] = incl;
    __syncthreads();
    if (w == 0) wsum[lane] = warp_iscan(wsum[lane], lane);
    __syncthreads();
    int off = (w > 0) ? wsum[w - 1] : 0;
    if (gid < n) g_rowptr[gid] = off + incl - v;
    if (tid == 0) g_bsum[blockIdx.x] = wsum[31];
}

__global__ void scan_tops(int nb, int n) {
    __shared__ int wsum[32];
    int tid = threadIdx.x;
    int lane = tid & 31;
    int w = tid >> 5;
    int v = (tid < nb) ? g_bsum[tid] : 0;
    int incl = warp_iscan(v, lane);
    if (lane == 31) wsum[w] = incl;
    __syncthreads();
    if (w == 0) wsum[lane] = warp_iscan(wsum[lane], lane);
    __syncthreads();
    int off = (w > 0) ? wsum[w - 1] : 0;
    if (tid < nb) g_boff[tid] = off + incl - v;
    if (tid == 0) g_rowptr[n] = wsum[31];
}

__global__ void scan_add(int n) {
    int tid = threadIdx.x;
    int gid = blockIdx.x * 1024 + tid;
    if (gid < n) {
        int r = g_rowptr[gid] + g_boff[blockIdx.x];
        g_rowptr[gid] = r;
        g_cursor[gid] = r;
        float d = fmaxf((float)g_cnt[gid], 1.0f);
        float iv = 1.0f / d;
        g_dinv[gid] = iv;
        g_dinv2[gid] = iv * iv;
    }
}

__global__ void scatter_kernel(const int* __restrict__ rows,
                               const int* __restrict__ cols, int E, int n) {
    int e = blockIdx.x * blockDim.x + threadIdx.x;
    if (e < E) {
        int r = rows[e];
        int c = cols[e];
        if ((unsigned)r < (unsigned)n && (unsigned)c < (unsigned)n) {
            int pos = atomicAdd(&g_cursor[r], 1);
            g_csrcol[pos] = c;
        }
    }
}

// ---------------- SpMM gather (no atomics) ----------------------------------
__global__ void spmm_gather(const float* __restrict__ src,
                            float* __restrict__ dst, int n) {
    int lane = threadIdx.x & 31;
    int warp = (blockIdx.x * blockDim.x + threadIdx.x) >> 5;
    int nw = (gridDim.x * blockDim.x) >> 5;
    for (int r = warp; r < n; r += nw) {
        int s = g_rowptr[r];
        int e = g_rowptr[r + 1];
        float4 a0 = make_float4(0.f, 0.f, 0.f, 0.f);
        float4 a1 = make_float4(0.f, 0.f, 0.f, 0.f);
        float4 a2 = make_float4(0.f, 0.f, 0.f, 0.f);
        float4 a3 = make_float4(0.f, 0.f, 0.f, 0.f);
        int j = s;
        for (; j + 3 < e; j += 4) {
            int c0 = g_csrcol[j + 0];
            int c1 = g_csrcol[j + 1];
            int c2 = g_csrcol[j + 2];
            int c3 = g_csrcol[j + 3];
            float4 v0 = *reinterpret_cast<const float4*>(src + (size_t)c0 * D + lane * 4);
            float4 v1 = *reinterpret_cast<const float4*>(src + (size_t)c1 * D + lane * 4);
            float4 v2 = *reinterpret_cast<const float4*>(src + (size_t)c2 * D + lane * 4);
            float4 v3 = *reinterpret_cast<const float4*>(src + (size_t)c3 * D + lane * 4);
            a0.x += v0.x; a0.y += v0.y; a0.z += v0.z; a0.w += v0.w;
            a1.x += v1.x; a1.y += v1.y; a1.z += v1.z; a1.w += v1.w;
            a2.x += v2.x; a2.y += v2.y; a2.z += v2.z; a2.w += v2.w;
            a3.x += v3.x; a3.y += v3.y; a3.z += v3.z; a3.w += v3.w;
        }
        for (; j < e; j++) {
            int c = g_csrcol[j];
            float4 v = *reinterpret_cast<const float4*>(src + (size_t)c * D + lane * 4);
            a0.x += v.x; a0.y += v.y; a0.z += v.z; a0.w += v.w;
        }
        float4 acc;
        acc.x = (a0.x + a1.x) + (a2.x + a3.x);
        acc.y = (a0.y + a1.y) + (a2.y + a3.y);
        acc.z = (a0.z + a1.z) + (a2.z + a3.z);
        acc.w = (a0.w + a1.w) + (a2.w + a3.w);
        *reinterpret_cast<float4*>(dst + (size_t)r * D + lane * 4) = acc;
    }
}

// ---------------- W hi/lo precompute (bf16 [k][n] row-major) ----------------
__global__ void wprep_kernel(const float* __restrict__ W0,
                             const float* __restrict__ W1,
                             const float* __restrict__ W2) {
    int b = blockIdx.y;
    const float* W = (b == 0) ? W0 : ((b == 1) ? W1 : W2);
    __nv_bfloat16* hi = reinterpret_cast<__nv_bfloat16*>(g_Whi4[b]);
    __nv_bfloat16* lo = reinterpret_cast<__nv_bfloat16*>(g_Wlo4[b]);
    int idx = blockIdx.x * blockDim.x + threadIdx.x;
    if (idx < 16384) {
        float v = W[idx];
        __nv_bfloat16 h = __float2bfloat16(v);
        __nv_bfloat16 l = __float2bfloat16(v - __bfloat162float(h));
        hi[idx] = h;
        lo[idx] = l;
    }
}

// ---------------- out init: broadcast b_cls ---------------------------------
__global__ void init_out(float* __restrict__ out, const float* __restrict__ bcls,
                         int n) {
    __shared__ float bc[16];
    if (threadIdx.x < 16) bc[threadIdx.x] = bcls[threadIdx.x];
    __syncthreads();
    int i = blockIdx.x * blockDim.x + threadIdx.x;
    if (i < n * 16) out[i] = bc[i & 15];
}

// ---------------- mma.sync fused branch GEMM (atomic out) -------------------
#define SM_AHI   0
#define SM_ALO   34816
#define SM_BHI   69632
#define SM_BLO   104448
#define SM_WC    139264
#define SM_BIAS  147456
#define SM_TOT   147968
#define ASTRIDE  272      // bytes per bf16 row (136 elems)

#define MMA_BF16(d, a, b) \
    asm volatile( \
        "mma.sync.aligned.m16n8k16.row.col.f32.bf16.bf16.f32 " \
        "{%0,%1,%2,%3}, {%4,%5,%6,%7}, {%8,%9}, {%0,%1,%2,%3};" \
        : "+f"((d)[0]), "+f"((d)[1]), "+f"((d)[2]), "+f"((d)[3]) \
        : "r"((a)[0]), "r"((a)[1]), "r"((a)[2]), "r"((a)[3]), \
          "r"((b)[0]), "r"((b)[1]))

#define LDSM_X4(r, addr) \
    asm volatile("ldmatrix.sync.aligned.m8n8.x4.shared.b16 {%0,%1,%2,%3}, [%4];" \
        : "=r"((r)[0]), "=r"((r)[1]), "=r"((r)[2]), "=r"((r)[3]) : "r"(addr))

#define LDSM_X4T(r, addr) \
    asm volatile("ldmatrix.sync.aligned.m8n8.x4.trans.shared.b16 {%0,%1,%2,%3}, [%4];" \
        : "=r"((r)[0]), "=r"((r)[1]), "=r"((r)[2]), "=r"((r)[3]) : "r"(addr))

__global__ void __launch_bounds__(256, 1)
gemm_mma(const float* __restrict__ A, const float* __restrict__ scale,
         const uint4* __restrict__ Whi, const uint4* __restrict__ Wlo,
         const float* __restrict__ bias, const float* __restrict__ Wc,
         float* __restrict__ out, int n) {
    extern __shared__ char smc[];
    uint32_t sb;
    asm("{ .reg .u64 t; cvta.to.shared.u64 t, %1; cvt.u32.u64 %0, t; }"
        : "=r"(sb) : "l"(smc));
    int tid = threadIdx.x;
    int wid = tid >> 5;
    int lane = tid & 31;
    int rowBase = blockIdx.x * 128;

    for (int i = tid; i < 512; i += 256)
        reinterpret_cast<float4*>(smc + SM_WC)[i] =
            reinterpret_cast<const float4*>(Wc)[i];
    if (tid < 128)
        reinterpret_cast<float*>(smc + SM_BIAS)[tid] = bias[tid];
    for (int i = tid; i < 2048; i += 256) {
        int k = i >> 4;
        int q = i & 15;
        *reinterpret_cast<uint4*>(smc + SM_BHI + k * ASTRIDE + q * 16) = Whi[i];
        *reinterpret_cast<uint4*>(smc + SM_BLO + k * ASTRIDE + q * 16) = Wlo[i];
    }
    for (int i4 = tid; i4 < 4096; i4 += 256) {
        int r = i4 >> 5;
        int c4 = (i4 & 31) << 2;
        int gr = rowBase + r;
        float4 v = make_float4(0.f, 0.f, 0.f, 0.f);
        if (gr < n) {
            v = *reinterpret_cast<const float4*>(A + (size_t)gr * 128 + c4);
            if (scale) {
                float s = scale[gr];
                v.x *= s; v.y *= s; v.z *= s; v.w *= s;
            }
        }
        __nv_bfloat16 h0 = __float2bfloat16(v.x);
        __nv_bfloat16 h1 = __float2bfloat16(v.y);
        __nv_bfloat16 h2 = __float2bfloat16(v.z);
        __nv_bfloat16 h3 = __float2bfloat16(v.w);
        __nv_bfloat162 ph0; ph0.x = h0; ph0.y = h1;
        __nv_bfloat162 ph1; ph1.x = h2; ph1.y = h3;
        __nv_bfloat162 pl0;
        pl0.x = __float2bfloat16(v.x - __bfloat162float(h0));
        pl0.y = __float2bfloat16(v.y - __bfloat162float(h1));
        __nv_bfloat162 pl1;
        pl1.x = __float2bfloat16(v.z - __bfloat162float(h2));
        pl1.y = __float2bfloat16(v.w - __bfloat162float(h3));
        char* pa = smc + r * ASTRIDE + c4 * 2;
        *reinterpret_cast<__nv_bfloat162*>(pa + SM_AHI) = ph0;
        *reinterpret_cast<__nv_bfloat162*>(pa + SM_AHI + 4) = ph1;
        *reinterpret_cast<__nv_bfloat162*>(pa + SM_ALO) = pl0;
        *reinterpret_cast<__nv_bfloat162*>(pa + SM_ALO + 4) = pl1;
    }
    __syncthreads();

    int mrow = (wid & 3) * 32;
    int ncol = (wid >> 2) * 64;

    float acc[2][8][4];
#pragma unroll
    for (int mt = 0; mt < 2; mt++)
#pragma unroll
        for (int nt = 0; nt < 8; nt++)
#pragma unroll
            for (int q = 0; q < 4; q++) acc[mt][nt][q] = 0.f;

    int arow = lane & 15;
    int acol8 = (lane >> 4) * 8;

#pragma unroll
    for (int ks = 0; ks < 8; ks++) {
        int k0 = ks * 16;
        uint32_t aHi[2][4], aLo[2][4], bHi[4][4], bLo[4][4];
#pragma unroll
        for (int mt = 0; mt < 2; mt++) {
            uint32_t ad = sb + (mrow + mt * 16 + arow) * ASTRIDE + (k0 + acol8) * 2;
            LDSM_X4(aHi[mt], ad + SM_AHI);
            LDSM_X4(aLo[mt], ad + SM_ALO);
        }
#pragma unroll
        for (int np = 0; np < 4; np++) {
            uint32_t bd = sb + (k0 + arow) * ASTRIDE + (ncol + np * 16 + acol8) * 2;
            LDSM_X4T(bHi[np], bd + SM_BHI);
            LDSM_X4T(bLo[np], bd + SM_BLO);
        }
#pragma unroll
        for (int mt = 0; mt < 2; mt++)
#pragma unroll
            for (int np = 0; np < 4; np++) {
                MMA_BF16(acc[mt][np * 2],     aHi[mt], bHi[np]);
                MMA_BF16(acc[mt][np * 2],     aHi[mt], bLo[np]);
                MMA_BF16(acc[mt][np * 2],     aLo[mt], bHi[np]);
                MMA_BF16(acc[mt][np * 2 + 1], aHi[mt], (bHi[np] + 2));
                MMA_BF16(acc[mt][np * 2 + 1], aHi[mt], (bLo[np] + 2));
                MMA_BF16(acc[mt][np * 2 + 1], aLo[mt], (bHi[np] + 2));
            }
    }
    __syncthreads();

    const float* sBias = reinterpret_cast<const float*>(smc + SM_BIAS);
    float* sRelu = reinterpret_cast<float*>(smc);
#pragma unroll
    for (int mt = 0; mt < 2; mt++)
#pragma unroll
        for (int nt = 0; nt < 8; nt++) {
            int col = ncol + nt * 8 + (lane & 3) * 2;
            float b0 = sBias[col], b1 = sBias[col + 1];
            int r0 = mrow + mt * 16 + (lane >> 2);
            sRelu[r0 * 133 + col]       = fmaxf(acc[mt][nt][0] + b0, 0.f);
            sRelu[r0 * 133 + col + 1]   = fmaxf(acc[mt][nt][1] + b1, 0.f);
            sRelu[(r0 + 8) * 133 + col]     = fmaxf(acc[mt][nt][2] + b0, 0.f);
            sRelu[(r0 + 8) * 133 + col + 1] = fmaxf(acc[mt][nt][3] + b1, 0.f);
        }
    __syncthreads();

    int m = tid >> 1;
    int jg = tid & 1;
    float c8[8];
#pragma unroll
    for (int j = 0; j < 8; j++) c8[j] = 0.f;
    const char* wcBase = smc + SM_WC + jg * 32;
#pragma unroll 8
    for (int nn = 0; nn < 128; nn++) {
        float h = sRelu[m * 133 + nn];
        float4 w0 = *reinterpret_cast<const float4*>(wcBase + nn * 64);
        float4 w1 = *reinterpret_cast<const float4*>(wcBase + nn * 64 + 16);
        c8[0] += h * w0.x; c8[1] += h * w0.y; c8[2] += h * w0.z; c8[3] += h * w0.w;
        c8[4] += h * w1.x; c8[5] += h * w1.y; c8[6] += h * w1.z; c8[7] += h * w1.w;
    }
    int gr = rowBase + m;
    if (gr < n) {
        float* o = out + (size_t)gr * 16 + jg * 8;
#pragma unroll
        for (int j = 0; j < 8; j++) atomicAdd(o + j, c8[j]);
    }
}

// ---------------- launcher (stream-forked for overlap) ----------------------
extern "C" void kernel_launch(void* const* d_in, const int* in_sizes, int n_in,
                              void* d_out, int out_size) {
    const float* x     = (const float*)d_in[0];
    const int*   ei    = (const int*)d_in[1];     // int32 (JAX x64 off)
    const float* W_ego = (const float*)d_in[2];
    const float* b_ego = (const float*)d_in[3];
    const float* W_h1  = (const float*)d_in[4];
    const float* b_h1  = (const float*)d_in[5];
    const float* W_h2  = (const float*)d_in[6];
    const float* b_h2  = (const float*)d_in[7];
    const float* W_cls = (const float*)d_in[8];
    const float* b_cls = (const float*)d_in[9];
    float* out = (float*)d_out;

    int n = in_sizes[0] / D;        // 100000
    int E = in_sizes[1] / 2;        // 1600000
    if (E > EMAX) E = EMAX;
    const int* rows = ei;
    const int* cols = ei + E;

    float *y1, *y2, *dinv, *dinv2;
    cudaGetSymbolAddress((void**)&y1, g_y1);
    cudaGetSymbolAddress((void**)&y2, g_y2);
    cudaGetSymbolAddress((void**)&dinv, g_dinv);
    cudaGetSymbolAddress((void**)&dinv2, g_dinv2);
    uint4 *whi, *wlo;
    cudaGetSymbolAddress((void**)&whi, g_Whi4);
    cudaGetSymbolAddress((void**)&wlo, g_Wlo4);

    // One-time stream/event setup (host handles only; created on the first,
    // uncaptured correctness call and reused under graph capture).
    static cudaStream_t s1 = nullptr, s2 = nullptr;
    static cudaEvent_t evW = nullptr, evY1 = nullptr, evG0 = nullptr, evG1 = nullptr;
    static int smemSet = 0;
    if (!s1) {
        cudaStreamCreateWithFlags(&s1, cudaStreamNonBlocking);
        cudaStreamCreateWithFlags(&s2, cudaStreamNonBlocking);
        cudaEventCreateWithFlags(&evW, cudaEventDisableTiming);
        cudaEventCreateWithFlags(&evY1, cudaEventDisableTiming);
        cudaEventCreateWithFlags(&evG0, cudaEventDisableTiming);
        cudaEventCreateWithFlags(&evG1, cudaEventDisableTiming);
    }
    if (!smemSet) {
        cudaFuncSetAttribute(gemm_mma,
                             cudaFuncAttributeMaxDynamicSharedMemorySize, SM_TOT);
        smemSet = 1;
    }

    int gb = (n + 127) / 128;
    int nb = (n + 1023) / 1024;     // 98

    // Origin stream: prep (needed by all gemms)
    wprep_kernel<<<dim3(64, 3), 256>>>(W_ego, W_h1, W_h2);
    init_out<<<(n * 16 + 255) / 256, 256>>>(out, b_cls, n);
    cudaEventRecord(evW, 0);

    // s1: ego gemm — depends only on x + prep; overlaps entire CSR/SpMM chain
    cudaStreamWaitEvent(s1, evW, 0);
    gemm_mma<<<gb, 256, SM_TOT, s1>>>(x, nullptr, whi, wlo, b_ego,
                                      W_cls, out, n);
    cudaEventRecord(evG0, s1);

    // Origin: CSR build + spmm1
    zero_cnt<<<nb, 1024>>>(n);
    count_kernel<<<(E + 255) / 256, 256>>>(rows, E, n);
    scan_blocks<<<nb, 1024>>>(n);
    scan_tops<<<1, 1024>>>(nb, n);
    scan_add<<<nb, 1024>>>(n);
    scatter_kernel<<<(E + 255) / 256, 256>>>(rows, cols, E, n);
    spmm_gather<<<12800, 256>>>(x, y1, n);
    cudaEventRecord(evY1, 0);

    // s2: h1 gemm — depends on y1 (+ dinv, ready earlier); overlaps spmm2
    cudaStreamWaitEvent(s2, evY1, 0);
    gemm_mma<<<gb, 256, SM_TOT, s2>>>(y1, dinv, whi + 2048, wlo + 2048, b_h1,
                                      W_cls + 128 * 16, out, n);
    cudaEventRecord(evG1, s2);

    // Origin: spmm2 + h2 gemm (critical path)
    spmm_gather<<<12800, 256>>>(y1, y2, n);
    gemm_mma<<<gb, 256, SM_TOT>>>(y2, dinv2, whi + 4096, wlo + 4096, b_h2,
                                  W_cls + 256 * 16, out, n);

    // Join side streams back into origin before returning
    cudaStreamWaitEvent(0, evG0, 0);
    cudaStreamWaitEvent(0, evG1, 0);
}